// round 2
// baseline (speedup 1.0000x reference)
#include <cuda_runtime.h>
#include <math.h>

#define D       128
#define D4      32
#define NMAX    50000
#define BK      16
#define NCHUNK  8            // D / BK
#define THREADS 256
#define ABUF    (BK * 128)   // floats per single buffer (2048)

// -------- device scratch (allocation-free rule: __device__ globals) --------
__device__ float g_x[NMAX * D];
__device__ float g_agg[NMAX * D];
__device__ float g_out[NMAX * D];
__device__ float g_z[NMAX * D];
__device__ float g_rx[NMAX * D];

// ---------------------------------------------------------------------------
// GEMM building blocks. Block tile 128x128, K chunked by 16, 256 threads,
// 8x8 micro-tile per thread (2x2 blocks of 4x4). Double-buffered SMEM:
// prefetch chunk k+1 into registers during compute of chunk k; ONE sync/chunk.
// ---------------------------------------------------------------------------

__device__ __forceinline__ void fma_8x8(float acc[8][8], float4 a0, float4 a1,
                                        float4 b0, float4 b1) {
    float av[8] = {a0.x, a0.y, a0.z, a0.w, a1.x, a1.y, a1.z, a1.w};
    float bv[8] = {b0.x, b0.y, b0.z, b0.w, b1.x, b1.y, b1.z, b1.w};
#pragma unroll
    for (int i = 0; i < 8; ++i)
#pragma unroll
        for (int j = 0; j < 8; ++j)
            acc[i][j] += av[i] * bv[j];
}

__device__ __forceinline__ void inner16(const float* As, const float* Bs,
                                        int tr, int tc, float acc[8][8]) {
#pragma unroll
    for (int k = 0; k < BK; ++k) {
        float4 a0 = reinterpret_cast<const float4*>(As)[k * 32 + tr];
        float4 a1 = reinterpret_cast<const float4*>(As)[k * 32 + 16 + tr];
        float4 b0 = reinterpret_cast<const float4*>(Bs)[k * 32 + tc];
        float4 b1 = reinterpret_cast<const float4*>(Bs)[k * 32 + 16 + tc];
        fma_8x8(acc, a0, a1, b0, b1);
    }
}

// ---- prefetch (LDG->regs) and commit (regs->SMEM) halves ----
__device__ __forceinline__ void ldg_A(const float* __restrict__ A, int row0,
                                      int Nrows, int k0, int tid, float4* pv) {
#pragma unroll
    for (int q = 0; q < 2; ++q) {
        int idx = tid + q * 256;
        int row = idx >> 2;
        int kq  = (idx & 3) << 2;
        float4 v = make_float4(0.f, 0.f, 0.f, 0.f);
        if (row0 + row < Nrows)
            v = reinterpret_cast<const float4*>(A)[(size_t)(row0 + row) * D4 + ((k0 + kq) >> 2)];
        pv[q] = v;
    }
}

__device__ __forceinline__ void sts_A(float* As, int tid, const float4* pv) {
#pragma unroll
    for (int q = 0; q < 2; ++q) {
        int idx = tid + q * 256;
        int row = idx >> 2;
        int kq  = (idx & 3) << 2;
        As[(kq + 0) * 128 + row] = pv[q].x;
        As[(kq + 1) * 128 + row] = pv[q].y;
        As[(kq + 2) * 128 + row] = pv[q].z;
        As[(kq + 3) * 128 + row] = pv[q].w;
    }
}

__device__ __forceinline__ void ldg_B(const float* __restrict__ W, int k0,
                                      int tid, float4* pv) {
#pragma unroll
    for (int q = 0; q < 2; ++q) {
        int idx = tid + q * 256;
        int k  = idx >> 5;
        int c4 = idx & 31;
        pv[q] = reinterpret_cast<const float4*>(W)[(size_t)(k0 + k) * D4 + c4];
    }
}

__device__ __forceinline__ void sts_B(float* Bs, int tid, const float4* pv) {
#pragma unroll
    for (int q = 0; q < 2; ++q) {
        int idx = tid + q * 256;
        int k  = idx >> 5;
        int c4 = idx & 31;
        reinterpret_cast<float4*>(Bs)[k * 32 + c4] = pv[q];
    }
}

// Full-K double-buffered GEMM accumulate: acc += A[row0:+128, :] @ W
// As/Bs point to 2*ABUF float double buffers.
__device__ __forceinline__ void gemm_db(const float* __restrict__ A,
                                        const float* __restrict__ W,
                                        int row0, int Nrows,
                                        float* As, float* Bs,
                                        int tid, int tr, int tc,
                                        float acc[8][8]) {
    float4 pa[2], pb[2];
    ldg_A(A, row0, Nrows, 0, tid, pa);
    ldg_B(W, 0, tid, pb);
    sts_A(As, tid, pa);
    sts_B(Bs, tid, pb);
    __syncthreads();
#pragma unroll
    for (int kc = 0; kc < NCHUNK; ++kc) {
        int cur = kc & 1;
        if (kc < NCHUNK - 1) {
            ldg_A(A, row0, Nrows, (kc + 1) * BK, tid, pa);
            ldg_B(W, (kc + 1) * BK, tid, pb);
        }
        inner16(As + cur * ABUF, Bs + cur * ABUF, tr, tc, acc);
        if (kc < NCHUNK - 1) {
            sts_A(As + (cur ^ 1) * ABUF, tid, pa);
            sts_B(Bs + (cur ^ 1) * ABUF, tid, pb);
            __syncthreads();
        }
    }
    // No trailing sync needed: next prologue writes buf0, whose last readers
    // finished before the sync at end of chunk NCHUNK-2.
}

__device__ __forceinline__ float sigf(float x) { return 1.0f / (1.0f + expf(-x)); }

// ---------------------------------------------------------------------------
// Fused 2-layer MLP: O = relu(A @ W1 + b1) @ W2 + b2
// Mid result H kept in SMEM (transposed, XOR-swizzled).
// ---------------------------------------------------------------------------
__global__ void __launch_bounds__(THREADS, 2)
mlp2_kernel(const float* __restrict__ A,
            const float* __restrict__ W1, const float* __restrict__ b1,
            const float* __restrict__ W2, const float* __restrict__ b2,
            float* __restrict__ O, int Nrows)
{
    extern __shared__ float sm[];
    float* As = sm;                     // 2 * 16*128
    float* Bs = sm + 2 * ABUF;          // 2 * 16*128
    float* Hs = sm + 4 * ABUF;          // 128*128

    int tid = threadIdx.x;
    int tr = tid >> 4, tc = tid & 15;
    int row0 = blockIdx.x * 128;

    float acc[8][8];
#pragma unroll
    for (int i = 0; i < 8; ++i)
#pragma unroll
        for (int j = 0; j < 8; ++j) acc[i][j] = 0.f;

    // ---- GEMM1 ----
    gemm_db(A, W1, row0, Nrows, As, Bs, tid, tr, tc, acc);

    // ---- epilogue1: relu(acc + b1) -> Hs (transposed + swizzled) ----
#pragma unroll
    for (int j = 0; j < 8; ++j) {
        int c = (j < 4) ? (tc * 4 + j) : (64 + tc * 4 + (j - 4));
        float bb = __ldg(&b1[c]);
        int sw = (c >> 2) & 7;
        float4 v0, v1;
        v0.x = fmaxf(acc[0][j] + bb, 0.f);
        v0.y = fmaxf(acc[1][j] + bb, 0.f);
        v0.z = fmaxf(acc[2][j] + bb, 0.f);
        v0.w = fmaxf(acc[3][j] + bb, 0.f);
        v1.x = fmaxf(acc[4][j] + bb, 0.f);
        v1.y = fmaxf(acc[5][j] + bb, 0.f);
        v1.z = fmaxf(acc[6][j] + bb, 0.f);
        v1.w = fmaxf(acc[7][j] + bb, 0.f);
        reinterpret_cast<float4*>(Hs)[c * 32 + (tr ^ sw)]      = v0;
        reinterpret_cast<float4*>(Hs)[c * 32 + (tr ^ sw) + 16] = v1;
    }

#pragma unroll
    for (int i = 0; i < 8; ++i)
#pragma unroll
        for (int j = 0; j < 8; ++j) acc[i][j] = 0.f;

    // ---- GEMM2: Hs @ W2 (only Bs double-buffered) ----
    {
        float4 pb[2];
        ldg_B(W2, 0, tid, pb);
        sts_B(Bs, tid, pb);
        __syncthreads();   // also publishes Hs
#pragma unroll
        for (int kc = 0; kc < NCHUNK; ++kc) {
            int cur = kc & 1;
            if (kc < NCHUNK - 1) ldg_B(W2, (kc + 1) * BK, tid, pb);
            const float* Bc = Bs + cur * ABUF;
#pragma unroll
            for (int k = 0; k < BK; ++k) {
                int kk = kc * BK + k;
                int sw = (kk >> 2) & 7;
                float4 a0 = reinterpret_cast<const float4*>(Hs)[kk * 32 + (tr ^ sw)];
                float4 a1 = reinterpret_cast<const float4*>(Hs)[kk * 32 + (tr ^ sw) + 16];
                float4 b0 = reinterpret_cast<const float4*>(Bc)[k * 32 + tc];
                float4 b1 = reinterpret_cast<const float4*>(Bc)[k * 32 + 16 + tc];
                fma_8x8(acc, a0, a1, b0, b1);
            }
            if (kc < NCHUNK - 1) {
                sts_B(Bs + (cur ^ 1) * ABUF, tid, pb);
                __syncthreads();
            }
        }
    }

    // ---- epilogue2: O = acc + b2 ----
    float bb0[4], bb1[4];
#pragma unroll
    for (int j = 0; j < 4; ++j) {
        bb0[j] = __ldg(&b2[tc * 4 + j]);
        bb1[j] = __ldg(&b2[64 + tc * 4 + j]);
    }
#pragma unroll
    for (int i = 0; i < 8; ++i) {
        int row = row0 + ((i < 4) ? (tr * 4 + i) : (64 + tr * 4 + (i - 4)));
        if (row < Nrows) {
            float4 o0 = make_float4(acc[i][0] + bb0[0], acc[i][1] + bb0[1],
                                    acc[i][2] + bb0[2], acc[i][3] + bb0[3]);
            float4 o1 = make_float4(acc[i][4] + bb1[0], acc[i][5] + bb1[1],
                                    acc[i][6] + bb1[2], acc[i][7] + bb1[3]);
            reinterpret_cast<float4*>(O)[(size_t)row * D4 + tc]      = o0;
            reinterpret_cast<float4*>(O)[(size_t)row * D4 + 16 + tc] = o1;
        }
    }
}

// ---------------------------------------------------------------------------
// Gate kernels: acc = A1 @ Wa + A2 @ Wb, mode-specific epilogue.
// ---------------------------------------------------------------------------
template <int MODE>
__global__ void __launch_bounds__(THREADS, 2)
gate_kernel(const float* __restrict__ A1, const float* __restrict__ Wa, const float* __restrict__ ba,
            const float* __restrict__ A2, const float* __restrict__ Wb, const float* __restrict__ bb_,
            float* __restrict__ O, int Nrows)
{
    __shared__ float As[2 * ABUF];
    __shared__ float Bs[2 * ABUF];
    int tid = threadIdx.x;
    int tr = tid >> 4, tc = tid & 15;
    int row0 = blockIdx.x * 128;

    float acc[8][8];
#pragma unroll
    for (int i = 0; i < 8; ++i)
#pragma unroll
        for (int j = 0; j < 8; ++j) acc[i][j] = 0.f;

    gemm_db(A1, Wa, row0, Nrows, As, Bs, tid, tr, tc, acc);
    gemm_db(A2, Wb, row0, Nrows, As, Bs, tid, tr, tc, acc);

    float bs0[4], bs1[4];
#pragma unroll
    for (int j = 0; j < 4; ++j) {
        bs0[j] = __ldg(&ba[tc * 4 + j]) + __ldg(&bb_[tc * 4 + j]);
        bs1[j] = __ldg(&ba[64 + tc * 4 + j]) + __ldg(&bb_[64 + tc * 4 + j]);
    }

#pragma unroll
    for (int i = 0; i < 8; ++i) {
        int row = row0 + ((i < 4) ? (tr * 4 + i) : (64 + tr * 4 + (i - 4)));
        if (row >= Nrows) continue;
        size_t p0 = (size_t)row * D4 + tc;
        size_t p1 = p0 + 16;
        float t0[4] = {acc[i][0] + bs0[0], acc[i][1] + bs0[1], acc[i][2] + bs0[2], acc[i][3] + bs0[3]};
        float t1[4] = {acc[i][4] + bs1[0], acc[i][5] + bs1[1], acc[i][6] + bs1[2], acc[i][7] + bs1[3]};

        if (MODE == 0) {
            reinterpret_cast<float4*>(g_z)[p0] = make_float4(sigf(t0[0]), sigf(t0[1]), sigf(t0[2]), sigf(t0[3]));
            reinterpret_cast<float4*>(g_z)[p1] = make_float4(sigf(t1[0]), sigf(t1[1]), sigf(t1[2]), sigf(t1[3]));
        } else if (MODE == 1) {
            float4 x0 = reinterpret_cast<const float4*>(g_x)[p0];
            float4 x1 = reinterpret_cast<const float4*>(g_x)[p1];
            reinterpret_cast<float4*>(g_rx)[p0] = make_float4(sigf(t0[0]) * x0.x, sigf(t0[1]) * x0.y,
                                                              sigf(t0[2]) * x0.z, sigf(t0[3]) * x0.w);
            reinterpret_cast<float4*>(g_rx)[p1] = make_float4(sigf(t1[0]) * x1.x, sigf(t1[1]) * x1.y,
                                                              sigf(t1[2]) * x1.z, sigf(t1[3]) * x1.w);
        } else {
            float4 x0 = reinterpret_cast<const float4*>(g_x)[p0];
            float4 x1 = reinterpret_cast<const float4*>(g_x)[p1];
            float4 z0 = reinterpret_cast<const float4*>(g_z)[p0];
            float4 z1 = reinterpret_cast<const float4*>(g_z)[p1];
            float4 o0, o1;
            o0.x = (1.f - z0.x) * x0.x + z0.x * tanhf(t0[0]);
            o0.y = (1.f - z0.y) * x0.y + z0.y * tanhf(t0[1]);
            o0.z = (1.f - z0.z) * x0.z + z0.z * tanhf(t0[2]);
            o0.w = (1.f - z0.w) * x0.w + z0.w * tanhf(t0[3]);
            o1.x = (1.f - z1.x) * x1.x + z1.x * tanhf(t1[0]);
            o1.y = (1.f - z1.y) * x1.y + z1.y * tanhf(t1[1]);
            o1.z = (1.f - z1.z) * x1.z + z1.z * tanhf(t1[2]);
            o1.w = (1.f - z1.w) * x1.w + z1.w * tanhf(t1[3]);
            reinterpret_cast<float4*>(O)[p0] = o0;
            reinterpret_cast<float4*>(O)[p1] = o1;
        }
    }
}

// ---------------------------------------------------------------------------
// Edge scatter: agg[rows[e]] += vals[e] * x[cols[e]]
// Warp per edge, vectorized red.global.add.v4.f32 (sm_90+), 2 edges in flight.
// ---------------------------------------------------------------------------
__device__ __forceinline__ void red4(float* p, float a, float b, float c, float d) {
    asm volatile("red.global.add.v4.f32 [%0], {%1, %2, %3, %4};"
                 :: "l"(p), "f"(a), "f"(b), "f"(c), "f"(d) : "memory");
}

__global__ void scatter_kernel(const int* __restrict__ rows, const int* __restrict__ cols,
                               const float* __restrict__ vals, const float* __restrict__ x,
                               float* __restrict__ agg, int E)
{
    int gw = (blockIdx.x * blockDim.x + threadIdx.x) >> 5;
    int lane = threadIdx.x & 31;
    int nw = (gridDim.x * blockDim.x) >> 5;
    const float4* x4 = reinterpret_cast<const float4*>(x);

    for (int e0 = gw * 2; e0 < E; e0 += nw * 2) {
        int e1 = e0 + 1;
        bool h1 = (e1 < E);
        int r0 = __ldg(&rows[e0]);
        int c0 = __ldg(&cols[e0]);
        float v0 = __ldg(&vals[e0]);
        int r1 = 0, c1 = 0;
        float v1 = 0.f;
        if (h1) { r1 = __ldg(&rows[e1]); c1 = __ldg(&cols[e1]); v1 = __ldg(&vals[e1]); }

        float4 a = x4[(size_t)c0 * D4 + lane];
        float4 b = h1 ? x4[(size_t)c1 * D4 + lane] : make_float4(0.f, 0.f, 0.f, 0.f);

        red4(agg + (size_t)r0 * D + lane * 4, v0 * a.x, v0 * a.y, v0 * a.z, v0 * a.w);
        if (h1)
            red4(agg + (size_t)r1 * D + lane * 4, v1 * b.x, v1 * b.y, v1 * b.z, v1 * b.w);
    }
}

__global__ void zero_kernel(float* __restrict__ p, int n4)
{
    int i = blockIdx.x * blockDim.x + threadIdx.x;
    if (i < n4) reinterpret_cast<float4*>(p)[i] = make_float4(0.f, 0.f, 0.f, 0.f);
}

// ---------------------------------------------------------------------------
extern "C" void kernel_launch(void* const* d_in, const int* in_sizes, int n_in,
                              void* d_out, int out_size)
{
    const float* x_in  = (const float*)d_in[0];
    const int*   rows  = (const int*)  d_in[1];
    const int*   cols  = (const int*)  d_in[2];
    const float* vals  = (const float*)d_in[3];
    const float* m1_W1 = (const float*)d_in[4];
    const float* m1_b1 = (const float*)d_in[5];
    const float* m1_W2 = (const float*)d_in[6];
    const float* m1_b2 = (const float*)d_in[7];
    const float* m2_W1 = (const float*)d_in[8];
    const float* m2_b1 = (const float*)d_in[9];
    const float* m2_W2 = (const float*)d_in[10];
    const float* m2_b2 = (const float*)d_in[11];
    const float* Wu1   = (const float*)d_in[12];
    const float* bu1   = (const float*)d_in[13];
    const float* Wu2   = (const float*)d_in[14];
    const float* bu2   = (const float*)d_in[15];
    const float* Wr1   = (const float*)d_in[16];
    const float* br1   = (const float*)d_in[17];
    const float* Wr2   = (const float*)d_in[18];
    const float* br2   = (const float*)d_in[19];
    const float* Wo1   = (const float*)d_in[20];
    const float* bo1   = (const float*)d_in[21];
    const float* Wo2   = (const float*)d_in[22];
    const float* bo2   = (const float*)d_in[23];

    int N = in_sizes[0] / D;
    int E = in_sizes[1];

    float *px, *pagg, *pout, *prx;
    cudaGetSymbolAddress((void**)&px,   g_x);
    cudaGetSymbolAddress((void**)&pagg, g_agg);
    cudaGetSymbolAddress((void**)&pout, g_out);
    cudaGetSymbolAddress((void**)&prx,  g_rx);

    int smem_mlp = (4 * ABUF + 128 * 128) * (int)sizeof(float);  // 96 KB
    cudaFuncSetAttribute(mlp2_kernel, cudaFuncAttributeMaxDynamicSharedMemorySize, smem_mlp);

    int nblk = (N + 127) / 128;
    int n4 = N * D / 4;

    zero_kernel<<<(n4 + 255) / 256, 256>>>(pagg, n4);
    mlp2_kernel<<<nblk, THREADS, smem_mlp>>>(x_in, m1_W1, m1_b1, m1_W2, m1_b2, px, N);
    scatter_kernel<<<2048, 256>>>(rows, cols, vals, px, pagg, E);
    mlp2_kernel<<<nblk, THREADS, smem_mlp>>>(pagg, m2_W1, m2_b1, m2_W2, m2_b2, pout, N);
    gate_kernel<0><<<nblk, THREADS>>>(pout, Wu1, bu1, px, Wu2, bu2, nullptr, N);
    gate_kernel<1><<<nblk, THREADS>>>(pout, Wr1, br1, px, Wr2, br2, nullptr, N);
    gate_kernel<2><<<nblk, THREADS>>>(pout, Wo1, bo1, prx, Wo2, bo2, (float*)d_out, N);
}

// round 3
// speedup vs baseline: 1.6825x; 1.6825x over previous
#include <cuda_runtime.h>
#include <math.h>

#define D    128
#define D4   32
#define NMAX 50000
#define BK   16
#define THREADS 256

// -------- device scratch (allocation-free rule: __device__ globals) --------
__device__ float g_x[NMAX * D];
__device__ float g_agg[NMAX * D];
__device__ float g_out[NMAX * D];
__device__ float g_z[NMAX * D];
__device__ float g_rx[NMAX * D];

// ---------------------------------------------------------------------------
// GEMM building blocks (R1-proven synchronous version).
// Block tile 128x128, K chunked by 16, 256 threads, 8x8 micro-tile per thread.
// ---------------------------------------------------------------------------

__device__ __forceinline__ void fma_8x8(float acc[8][8], float4 a0, float4 a1,
                                        float4 b0, float4 b1) {
    float av[8] = {a0.x, a0.y, a0.z, a0.w, a1.x, a1.y, a1.z, a1.w};
    float bv[8] = {b0.x, b0.y, b0.z, b0.w, b1.x, b1.y, b1.z, b1.w};
#pragma unroll
    for (int i = 0; i < 8; ++i)
#pragma unroll
        for (int j = 0; j < 8; ++j)
            acc[i][j] += av[i] * bv[j];
}

// Load A chunk [row0..row0+128) x [k0..k0+16) transposed into As[k][r].
template <bool GUARD>
__device__ __forceinline__ void load_As(const float* __restrict__ A, int row0,
                                        int Nrows, int k0, float* As, int tid) {
#pragma unroll
    for (int q = 0; q < 2; ++q) {
        int idx = tid + q * 256;       // 0..511
        int row = idx >> 2;            // 0..127
        int kq  = (idx & 3) << 2;      // 0,4,8,12
        float4 v = make_float4(0.f, 0.f, 0.f, 0.f);
        if (!GUARD || (row0 + row < Nrows))
            v = reinterpret_cast<const float4*>(A)[(size_t)(row0 + row) * D4 + ((k0 + kq) >> 2)];
        As[(kq + 0) * 128 + row] = v.x;
        As[(kq + 1) * 128 + row] = v.y;
        As[(kq + 2) * 128 + row] = v.z;
        As[(kq + 3) * 128 + row] = v.w;
    }
}

// Load W chunk [k0..k0+16) x [0..128) into Bs[k][c] (direct copy, coalesced).
__device__ __forceinline__ void load_Bs(const float* __restrict__ W, int k0,
                                        float* Bs, int tid) {
#pragma unroll
    for (int q = 0; q < 2; ++q) {
        int idx = tid + q * 256;
        int k  = idx >> 5;
        int c4 = idx & 31;
        reinterpret_cast<float4*>(Bs)[k * 32 + c4] =
            reinterpret_cast<const float4*>(W)[(size_t)(k0 + k) * D4 + c4];
    }
}

__device__ __forceinline__ void inner16(const float* As, const float* Bs,
                                        int tr, int tc, float acc[8][8]) {
#pragma unroll
    for (int k = 0; k < BK; ++k) {
        float4 a0 = reinterpret_cast<const float4*>(As)[k * 32 + tr];
        float4 a1 = reinterpret_cast<const float4*>(As)[k * 32 + 16 + tr];
        float4 b0 = reinterpret_cast<const float4*>(Bs)[k * 32 + tc];
        float4 b1 = reinterpret_cast<const float4*>(Bs)[k * 32 + 16 + tc];
        fma_8x8(acc, a0, a1, b0, b1);
    }
}

// Full-K GEMM accumulate: acc += A[row0:+128, :] @ W
__device__ __forceinline__ void gemm_global(const float* __restrict__ A,
                                            const float* __restrict__ W,
                                            int row0, int Nrows,
                                            float* As, float* Bs,
                                            int tid, int tr, int tc,
                                            float acc[8][8]) {
    if (row0 + 128 <= Nrows) {
        for (int kc = 0; kc < D; kc += BK) {
            load_As<false>(A, row0, Nrows, kc, As, tid);
            load_Bs(W, kc, Bs, tid);
            __syncthreads();
            inner16(As, Bs, tr, tc, acc);
            __syncthreads();
        }
    } else {
        for (int kc = 0; kc < D; kc += BK) {
            load_As<true>(A, row0, Nrows, kc, As, tid);
            load_Bs(W, kc, Bs, tid);
            __syncthreads();
            inner16(As, Bs, tr, tc, acc);
            __syncthreads();
        }
    }
}

__device__ __forceinline__ float sigf(float x) { return 1.0f / (1.0f + expf(-x)); }

// ---------------------------------------------------------------------------
// Fused 2-layer MLP: O = relu(A @ W1 + b1) @ W2 + b2
// Mid result H kept in SMEM (transposed, XOR-swizzled) — no global traffic.
// ---------------------------------------------------------------------------
__global__ void __launch_bounds__(THREADS, 2)
mlp2_kernel(const float* __restrict__ A,
            const float* __restrict__ W1, const float* __restrict__ b1,
            const float* __restrict__ W2, const float* __restrict__ b2,
            float* __restrict__ O, int Nrows)
{
    extern __shared__ float sm[];
    float* As = sm;                 // 16*128
    float* Bs = sm + BK * 128;      // 16*128
    float* Hs = sm + 2 * BK * 128;  // 128*128

    int tid = threadIdx.x;
    int tr = tid >> 4, tc = tid & 15;
    int row0 = blockIdx.x * 128;

    float acc[8][8];
#pragma unroll
    for (int i = 0; i < 8; ++i)
#pragma unroll
        for (int j = 0; j < 8; ++j) acc[i][j] = 0.f;

    // ---- GEMM1: A @ W1 ----
    gemm_global(A, W1, row0, Nrows, As, Bs, tid, tr, tc, acc);

    // ---- epilogue1: relu(acc + b1) -> Hs (transposed + swizzled) ----
#pragma unroll
    for (int j = 0; j < 8; ++j) {
        int c = (j < 4) ? (tc * 4 + j) : (64 + tc * 4 + (j - 4));
        float bb = __ldg(&b1[c]);
        int sw = (c >> 2) & 7;
        float4 v0, v1;
        v0.x = fmaxf(acc[0][j] + bb, 0.f);
        v0.y = fmaxf(acc[1][j] + bb, 0.f);
        v0.z = fmaxf(acc[2][j] + bb, 0.f);
        v0.w = fmaxf(acc[3][j] + bb, 0.f);
        v1.x = fmaxf(acc[4][j] + bb, 0.f);
        v1.y = fmaxf(acc[5][j] + bb, 0.f);
        v1.z = fmaxf(acc[6][j] + bb, 0.f);
        v1.w = fmaxf(acc[7][j] + bb, 0.f);
        reinterpret_cast<float4*>(Hs)[c * 32 + (tr ^ sw)]      = v0;
        reinterpret_cast<float4*>(Hs)[c * 32 + (tr ^ sw) + 16] = v1;
    }
    __syncthreads();

#pragma unroll
    for (int i = 0; i < 8; ++i)
#pragma unroll
        for (int j = 0; j < 8; ++j) acc[i][j] = 0.f;

    // ---- GEMM2: Hs @ W2 ----
    for (int kc = 0; kc < D; kc += BK) {
        load_Bs(W2, kc, Bs, tid);
        __syncthreads();
#pragma unroll
        for (int k = 0; k < BK; ++k) {
            int kk = kc + k;
            int sw = (kk >> 2) & 7;
            float4 a0 = reinterpret_cast<const float4*>(Hs)[kk * 32 + (tr ^ sw)];
            float4 a1 = reinterpret_cast<const float4*>(Hs)[kk * 32 + (tr ^ sw) + 16];
            float4 b0 = reinterpret_cast<const float4*>(Bs)[k * 32 + tc];
            float4 b1 = reinterpret_cast<const float4*>(Bs)[k * 32 + 16 + tc];
            fma_8x8(acc, a0, a1, b0, b1);
        }
        __syncthreads();
    }

    // ---- epilogue2: O = acc + b2 ----
    float bb0[4], bb1[4];
#pragma unroll
    for (int j = 0; j < 4; ++j) {
        bb0[j] = __ldg(&b2[tc * 4 + j]);
        bb1[j] = __ldg(&b2[64 + tc * 4 + j]);
    }
#pragma unroll
    for (int i = 0; i < 8; ++i) {
        int row = row0 + ((i < 4) ? (tr * 4 + i) : (64 + tr * 4 + (i - 4)));
        if (row < Nrows) {
            float4 o0 = make_float4(acc[i][0] + bb0[0], acc[i][1] + bb0[1],
                                    acc[i][2] + bb0[2], acc[i][3] + bb0[3]);
            float4 o1 = make_float4(acc[i][4] + bb1[0], acc[i][5] + bb1[1],
                                    acc[i][6] + bb1[2], acc[i][7] + bb1[3]);
            reinterpret_cast<float4*>(O)[(size_t)row * D4 + tc]      = o0;
            reinterpret_cast<float4*>(O)[(size_t)row * D4 + 16 + tc] = o1;
        }
    }
}

// ---------------------------------------------------------------------------
// Gate kernels: acc = A1 @ Wa + A2 @ Wb, then mode-specific epilogue.
//  MODE 0: g_z  = sigmoid(acc + ba + bb)
//  MODE 1: g_rx = sigmoid(acc + ba + bb) * g_x
//  MODE 2: O    = (1-g_z)*g_x + g_z*tanh(acc + ba + bb)
// ---------------------------------------------------------------------------
template <int MODE>
__global__ void __launch_bounds__(THREADS, 2)
gate_kernel(const float* __restrict__ A1, const float* __restrict__ Wa, const float* __restrict__ ba,
            const float* __restrict__ A2, const float* __restrict__ Wb, const float* __restrict__ bb_,
            float* __restrict__ O, int Nrows)
{
    __shared__ float As[BK * 128];
    __shared__ float Bs[BK * 128];
    int tid = threadIdx.x;
    int tr = tid >> 4, tc = tid & 15;
    int row0 = blockIdx.x * 128;

    float acc[8][8];
#pragma unroll
    for (int i = 0; i < 8; ++i)
#pragma unroll
        for (int j = 0; j < 8; ++j) acc[i][j] = 0.f;

    gemm_global(A1, Wa, row0, Nrows, As, Bs, tid, tr, tc, acc);
    gemm_global(A2, Wb, row0, Nrows, As, Bs, tid, tr, tc, acc);

    float bs0[4], bs1[4];
#pragma unroll
    for (int j = 0; j < 4; ++j) {
        bs0[j] = __ldg(&ba[tc * 4 + j]) + __ldg(&bb_[tc * 4 + j]);
        bs1[j] = __ldg(&ba[64 + tc * 4 + j]) + __ldg(&bb_[64 + tc * 4 + j]);
    }

#pragma unroll
    for (int i = 0; i < 8; ++i) {
        int row = row0 + ((i < 4) ? (tr * 4 + i) : (64 + tr * 4 + (i - 4)));
        if (row >= Nrows) continue;
        size_t p0 = (size_t)row * D4 + tc;
        size_t p1 = p0 + 16;
        float t0[4] = {acc[i][0] + bs0[0], acc[i][1] + bs0[1], acc[i][2] + bs0[2], acc[i][3] + bs0[3]};
        float t1[4] = {acc[i][4] + bs1[0], acc[i][5] + bs1[1], acc[i][6] + bs1[2], acc[i][7] + bs1[3]};

        if (MODE == 0) {
            reinterpret_cast<float4*>(g_z)[p0] = make_float4(sigf(t0[0]), sigf(t0[1]), sigf(t0[2]), sigf(t0[3]));
            reinterpret_cast<float4*>(g_z)[p1] = make_float4(sigf(t1[0]), sigf(t1[1]), sigf(t1[2]), sigf(t1[3]));
        } else if (MODE == 1) {
            float4 x0 = reinterpret_cast<const float4*>(g_x)[p0];
            float4 x1 = reinterpret_cast<const float4*>(g_x)[p1];
            reinterpret_cast<float4*>(g_rx)[p0] = make_float4(sigf(t0[0]) * x0.x, sigf(t0[1]) * x0.y,
                                                              sigf(t0[2]) * x0.z, sigf(t0[3]) * x0.w);
            reinterpret_cast<float4*>(g_rx)[p1] = make_float4(sigf(t1[0]) * x1.x, sigf(t1[1]) * x1.y,
                                                              sigf(t1[2]) * x1.z, sigf(t1[3]) * x1.w);
        } else {
            float4 x0 = reinterpret_cast<const float4*>(g_x)[p0];
            float4 x1 = reinterpret_cast<const float4*>(g_x)[p1];
            float4 z0 = reinterpret_cast<const float4*>(g_z)[p0];
            float4 z1 = reinterpret_cast<const float4*>(g_z)[p1];
            float4 o0, o1;
            o0.x = (1.f - z0.x) * x0.x + z0.x * tanhf(t0[0]);
            o0.y = (1.f - z0.y) * x0.y + z0.y * tanhf(t0[1]);
            o0.z = (1.f - z0.z) * x0.z + z0.z * tanhf(t0[2]);
            o0.w = (1.f - z0.w) * x0.w + z0.w * tanhf(t0[3]);
            o1.x = (1.f - z1.x) * x1.x + z1.x * tanhf(t1[0]);
            o1.y = (1.f - z1.y) * x1.y + z1.y * tanhf(t1[1]);
            o1.z = (1.f - z1.z) * x1.z + z1.z * tanhf(t1[2]);
            o1.w = (1.f - z1.w) * x1.w + z1.w * tanhf(t1[3]);
            reinterpret_cast<float4*>(O)[p0] = o0;
            reinterpret_cast<float4*>(O)[p1] = o1;
        }
    }
}

// ---------------------------------------------------------------------------
// Edge scatter: agg[rows[e]] += vals[e] * x[cols[e]]
// Warp per edge, vectorized red.global.add.v4.f32 (sm_90+), 2 edges in flight.
// ---------------------------------------------------------------------------
__device__ __forceinline__ void red4(float* p, float a, float b, float c, float d) {
    asm volatile("red.global.add.v4.f32 [%0], {%1, %2, %3, %4};"
                 :: "l"(p), "f"(a), "f"(b), "f"(c), "f"(d) : "memory");
}

__global__ void scatter_kernel(const int* __restrict__ rows, const int* __restrict__ cols,
                               const float* __restrict__ vals, const float* __restrict__ x,
                               float* __restrict__ agg, int E)
{
    int gw = (blockIdx.x * blockDim.x + threadIdx.x) >> 5;
    int lane = threadIdx.x & 31;
    int nw = (gridDim.x * blockDim.x) >> 5;
    const float4* x4 = reinterpret_cast<const float4*>(x);

    for (int e0 = gw * 2; e0 < E; e0 += nw * 2) {
        int e1 = e0 + 1;
        bool h1 = (e1 < E);
        int r0 = __ldg(&rows[e0]);
        int c0 = __ldg(&cols[e0]);
        float v0 = __ldg(&vals[e0]);
        int r1 = 0, c1 = 0;
        float v1 = 0.f;
        if (h1) { r1 = __ldg(&rows[e1]); c1 = __ldg(&cols[e1]); v1 = __ldg(&vals[e1]); }

        float4 a = x4[(size_t)c0 * D4 + lane];
        float4 b = h1 ? x4[(size_t)c1 * D4 + lane] : make_float4(0.f, 0.f, 0.f, 0.f);

        red4(agg + (size_t)r0 * D + lane * 4, v0 * a.x, v0 * a.y, v0 * a.z, v0 * a.w);
        if (h1)
            red4(agg + (size_t)r1 * D + lane * 4, v1 * b.x, v1 * b.y, v1 * b.z, v1 * b.w);
    }
}

__global__ void zero_kernel(float* __restrict__ p, int n4)
{
    int i = blockIdx.x * blockDim.x + threadIdx.x;
    if (i < n4) reinterpret_cast<float4*>(p)[i] = make_float4(0.f, 0.f, 0.f, 0.f);
}

// ---------------------------------------------------------------------------
extern "C" void kernel_launch(void* const* d_in, const int* in_sizes, int n_in,
                              void* d_out, int out_size)
{
    const float* x_in  = (const float*)d_in[0];
    const int*   rows  = (const int*)  d_in[1];
    const int*   cols  = (const int*)  d_in[2];
    const float* vals  = (const float*)d_in[3];
    const float* m1_W1 = (const float*)d_in[4];
    const float* m1_b1 = (const float*)d_in[5];
    const float* m1_W2 = (const float*)d_in[6];
    const float* m1_b2 = (const float*)d_in[7];
    const float* m2_W1 = (const float*)d_in[8];
    const float* m2_b1 = (const float*)d_in[9];
    const float* m2_W2 = (const float*)d_in[10];
    const float* m2_b2 = (const float*)d_in[11];
    const float* Wu1   = (const float*)d_in[12];
    const float* bu1   = (const float*)d_in[13];
    const float* Wu2   = (const float*)d_in[14];
    const float* bu2   = (const float*)d_in[15];
    const float* Wr1   = (const float*)d_in[16];
    const float* br1   = (const float*)d_in[17];
    const float* Wr2   = (const float*)d_in[18];
    const float* br2   = (const float*)d_in[19];
    const float* Wo1   = (const float*)d_in[20];
    const float* bo1   = (const float*)d_in[21];
    const float* Wo2   = (const float*)d_in[22];
    const float* bo2   = (const float*)d_in[23];

    int N = in_sizes[0] / D;
    int E = in_sizes[1];

    float *px, *pagg, *pout, *prx;
    cudaGetSymbolAddress((void**)&px,   g_x);
    cudaGetSymbolAddress((void**)&pagg, g_agg);
    cudaGetSymbolAddress((void**)&pout, g_out);
    cudaGetSymbolAddress((void**)&prx,  g_rx);

    int smem_mlp = (2 * BK * 128 + 128 * 128) * (int)sizeof(float);  // 80 KB
    cudaFuncSetAttribute(mlp2_kernel, cudaFuncAttributeMaxDynamicSharedMemorySize, smem_mlp);

    int nblk = (N + 127) / 128;
    int n4 = N * D / 4;

    zero_kernel<<<(n4 + 255) / 256, 256>>>(pagg, n4);
    mlp2_kernel<<<nblk, THREADS, smem_mlp>>>(x_in, m1_W1, m1_b1, m1_W2, m1_b2, px, N);
    scatter_kernel<<<2048, 256>>>(rows, cols, vals, px, pagg, E);
    mlp2_kernel<<<nblk, THREADS, smem_mlp>>>(pagg, m2_W1, m2_b1, m2_W2, m2_b2, pout, N);
    gate_kernel<0><<<nblk, THREADS>>>(pout, Wu1, bu1, px, Wu2, bu2, nullptr, N);
    gate_kernel<1><<<nblk, THREADS>>>(pout, Wr1, br1, px, Wr2, br2, nullptr, N);
    gate_kernel<2><<<nblk, THREADS>>>(pout, Wo1, bo1, prx, Wo2, bo2, (float*)d_out, N);
}

// round 4
// speedup vs baseline: 2.1429x; 1.2737x over previous
#include <cuda_runtime.h>
#include <math.h>
#include <stdint.h>

#define D    128
#define D4   32
#define NMAX 50000
#define BK   16
#define THREADS 256
#define SA   136   // smem row stride (floats) for tf32 tiles: 136 % 32 == 8 -> conflict-free frags

// -------- device scratch (allocation-free rule: __device__ globals) --------
__device__ float g_x[NMAX * D];
__device__ float g_agg[NMAX * D];
__device__ float g_out[NMAX * D];
__device__ float g_z[NMAX * D];
__device__ float g_rx[NMAX * D];

__device__ __forceinline__ float sigf(float x) { return 1.0f / (1.0f + expf(-x)); }

// ===========================================================================
// FP32 SIMT GEMM pieces (R3-proven) — used by mlp2 only.
// ===========================================================================

__device__ __forceinline__ void fma_8x8(float acc[8][8], float4 a0, float4 a1,
                                        float4 b0, float4 b1) {
    float av[8] = {a0.x, a0.y, a0.z, a0.w, a1.x, a1.y, a1.z, a1.w};
    float bv[8] = {b0.x, b0.y, b0.z, b0.w, b1.x, b1.y, b1.z, b1.w};
#pragma unroll
    for (int i = 0; i < 8; ++i)
#pragma unroll
        for (int j = 0; j < 8; ++j)
            acc[i][j] += av[i] * bv[j];
}

template <bool GUARD>
__device__ __forceinline__ void load_As(const float* __restrict__ A, int row0,
                                        int Nrows, int k0, float* As, int tid) {
#pragma unroll
    for (int q = 0; q < 2; ++q) {
        int idx = tid + q * 256;
        int row = idx >> 2;
        int kq  = (idx & 3) << 2;
        float4 v = make_float4(0.f, 0.f, 0.f, 0.f);
        if (!GUARD || (row0 + row < Nrows))
            v = reinterpret_cast<const float4*>(A)[(size_t)(row0 + row) * D4 + ((k0 + kq) >> 2)];
        As[(kq + 0) * 128 + row] = v.x;
        As[(kq + 1) * 128 + row] = v.y;
        As[(kq + 2) * 128 + row] = v.z;
        As[(kq + 3) * 128 + row] = v.w;
    }
}

__device__ __forceinline__ void load_Bs(const float* __restrict__ W, int k0,
                                        float* Bs, int tid) {
#pragma unroll
    for (int q = 0; q < 2; ++q) {
        int idx = tid + q * 256;
        int k  = idx >> 5;
        int c4 = idx & 31;
        reinterpret_cast<float4*>(Bs)[k * 32 + c4] =
            reinterpret_cast<const float4*>(W)[(size_t)(k0 + k) * D4 + c4];
    }
}

__device__ __forceinline__ void inner16(const float* As, const float* Bs,
                                        int tr, int tc, float acc[8][8]) {
#pragma unroll
    for (int k = 0; k < BK; ++k) {
        float4 a0 = reinterpret_cast<const float4*>(As)[k * 32 + tr];
        float4 a1 = reinterpret_cast<const float4*>(As)[k * 32 + 16 + tr];
        float4 b0 = reinterpret_cast<const float4*>(Bs)[k * 32 + tc];
        float4 b1 = reinterpret_cast<const float4*>(Bs)[k * 32 + 16 + tc];
        fma_8x8(acc, a0, a1, b0, b1);
    }
}

__device__ __forceinline__ void gemm_global(const float* __restrict__ A,
                                            const float* __restrict__ W,
                                            int row0, int Nrows,
                                            float* As, float* Bs,
                                            int tid, int tr, int tc,
                                            float acc[8][8]) {
    if (row0 + 128 <= Nrows) {
        for (int kc = 0; kc < D; kc += BK) {
            load_As<false>(A, row0, Nrows, kc, As, tid);
            load_Bs(W, kc, Bs, tid);
            __syncthreads();
            inner16(As, Bs, tr, tc, acc);
            __syncthreads();
        }
    } else {
        for (int kc = 0; kc < D; kc += BK) {
            load_As<true>(A, row0, Nrows, kc, As, tid);
            load_Bs(W, kc, Bs, tid);
            __syncthreads();
            inner16(As, Bs, tr, tc, acc);
            __syncthreads();
        }
    }
}

// ===========================================================================
// Fused 2-layer MLP (fp32 exact, unchanged from R3)
// ===========================================================================
__global__ void __launch_bounds__(THREADS, 2)
mlp2_kernel(const float* __restrict__ A,
            const float* __restrict__ W1, const float* __restrict__ b1,
            const float* __restrict__ W2, const float* __restrict__ b2,
            float* __restrict__ O, int Nrows)
{
    extern __shared__ float sm[];
    float* As = sm;
    float* Bs = sm + BK * 128;
    float* Hs = sm + 2 * BK * 128;

    int tid = threadIdx.x;
    int tr = tid >> 4, tc = tid & 15;
    int row0 = blockIdx.x * 128;

    float acc[8][8];
#pragma unroll
    for (int i = 0; i < 8; ++i)
#pragma unroll
        for (int j = 0; j < 8; ++j) acc[i][j] = 0.f;

    gemm_global(A, W1, row0, Nrows, As, Bs, tid, tr, tc, acc);

#pragma unroll
    for (int j = 0; j < 8; ++j) {
        int c = (j < 4) ? (tc * 4 + j) : (64 + tc * 4 + (j - 4));
        float bb = __ldg(&b1[c]);
        int sw = (c >> 2) & 7;
        float4 v0, v1;
        v0.x = fmaxf(acc[0][j] + bb, 0.f);
        v0.y = fmaxf(acc[1][j] + bb, 0.f);
        v0.z = fmaxf(acc[2][j] + bb, 0.f);
        v0.w = fmaxf(acc[3][j] + bb, 0.f);
        v1.x = fmaxf(acc[4][j] + bb, 0.f);
        v1.y = fmaxf(acc[5][j] + bb, 0.f);
        v1.z = fmaxf(acc[6][j] + bb, 0.f);
        v1.w = fmaxf(acc[7][j] + bb, 0.f);
        reinterpret_cast<float4*>(Hs)[c * 32 + (tr ^ sw)]      = v0;
        reinterpret_cast<float4*>(Hs)[c * 32 + (tr ^ sw) + 16] = v1;
    }
    __syncthreads();

#pragma unroll
    for (int i = 0; i < 8; ++i)
#pragma unroll
        for (int j = 0; j < 8; ++j) acc[i][j] = 0.f;

    for (int kc = 0; kc < D; kc += BK) {
        load_Bs(W2, kc, Bs, tid);
        __syncthreads();
#pragma unroll
        for (int k = 0; k < BK; ++k) {
            int kk = kc + k;
            int sw = (kk >> 2) & 7;
            float4 a0 = reinterpret_cast<const float4*>(Hs)[kk * 32 + (tr ^ sw)];
            float4 a1 = reinterpret_cast<const float4*>(Hs)[kk * 32 + (tr ^ sw) + 16];
            float4 b0 = reinterpret_cast<const float4*>(Bs)[k * 32 + tc];
            float4 b1 = reinterpret_cast<const float4*>(Bs)[k * 32 + 16 + tc];
            fma_8x8(acc, a0, a1, b0, b1);
        }
        __syncthreads();
    }

    float bb0[4], bb1[4];
#pragma unroll
    for (int j = 0; j < 4; ++j) {
        bb0[j] = __ldg(&b2[tc * 4 + j]);
        bb1[j] = __ldg(&b2[64 + tc * 4 + j]);
    }
#pragma unroll
    for (int i = 0; i < 8; ++i) {
        int row = row0 + ((i < 4) ? (tr * 4 + i) : (64 + tr * 4 + (i - 4)));
        if (row < Nrows) {
            float4 o0 = make_float4(acc[i][0] + bb0[0], acc[i][1] + bb0[1],
                                    acc[i][2] + bb0[2], acc[i][3] + bb0[3]);
            float4 o1 = make_float4(acc[i][4] + bb1[0], acc[i][5] + bb1[1],
                                    acc[i][6] + bb1[2], acc[i][7] + bb1[3]);
            reinterpret_cast<float4*>(O)[(size_t)row * D4 + tc]      = o0;
            reinterpret_cast<float4*>(O)[(size_t)row * D4 + 16 + tc] = o1;
        }
    }
}

// ===========================================================================
// TF32 tensor-core gate kernels.
// acc = A1 @ Wa + A2 @ Wb via mma.sync.m16n8k8 (tf32 in, fp32 accum).
// Block 128x128, 8 warps: warp grid 4(M) x 2(N); warp tile 32x64
//   = 2 m-tiles (m16) x 8 n-tiles (n8), 64 fp32 acc regs / thread.
// SMEM tiles stride SA=136 floats -> fragment LDS bank = (8*tig + g) % 32,
// bijective over the warp: conflict-free.
// ===========================================================================

__device__ __forceinline__ uint32_t f2tf32(float f) {
    uint32_t u;
    asm("cvt.rna.tf32.f32 %0, %1;" : "=r"(u) : "f"(f));
    return u;
}

__device__ __forceinline__ void mma_tf32(float c[4], const uint32_t a[4],
                                         uint32_t b0, uint32_t b1) {
    asm volatile(
        "mma.sync.aligned.m16n8k8.row.col.f32.tf32.tf32.f32 "
        "{%0,%1,%2,%3}, {%4,%5,%6,%7}, {%8,%9}, {%0,%1,%2,%3};"
        : "+f"(c[0]), "+f"(c[1]), "+f"(c[2]), "+f"(c[3])
        : "r"(a[0]), "r"(a[1]), "r"(a[2]), "r"(a[3]), "r"(b0), "r"(b1));
}

// A chunk [row0..+128) x [k0..+16) transposed into As[k][row], tf32-rounded.
__device__ __forceinline__ void load_As_tf(const float* __restrict__ A, int row0,
                                           int Nrows, int k0, float* As, int tid) {
#pragma unroll
    for (int q = 0; q < 2; ++q) {
        int idx = tid + q * 256;
        int row = idx >> 2;
        int kq  = (idx & 3) << 2;
        float4 v = make_float4(0.f, 0.f, 0.f, 0.f);
        if (row0 + row < Nrows)
            v = reinterpret_cast<const float4*>(A)[(size_t)(row0 + row) * D4 + ((k0 + kq) >> 2)];
        As[(kq + 0) * SA + row] = __uint_as_float(f2tf32(v.x));
        As[(kq + 1) * SA + row] = __uint_as_float(f2tf32(v.y));
        As[(kq + 2) * SA + row] = __uint_as_float(f2tf32(v.z));
        As[(kq + 3) * SA + row] = __uint_as_float(f2tf32(v.w));
    }
}

// W chunk [k0..+16) x [0..128) into Bs[k][c] (k-major), tf32-rounded.
__device__ __forceinline__ void load_Bs_tf(const float* __restrict__ W, int k0,
                                           float* Bs, int tid) {
#pragma unroll
    for (int q = 0; q < 2; ++q) {
        int idx = tid + q * 256;
        int k  = idx >> 5;
        int c4 = idx & 31;
        float4 v = reinterpret_cast<const float4*>(W)[(size_t)(k0 + k) * D4 + c4];
        float4 t;
        t.x = __uint_as_float(f2tf32(v.x));
        t.y = __uint_as_float(f2tf32(v.y));
        t.z = __uint_as_float(f2tf32(v.z));
        t.w = __uint_as_float(f2tf32(v.w));
        *reinterpret_cast<float4*>(&Bs[k * SA + c4 * 4]) = t;
    }
}

template <int MODE>
__global__ void __launch_bounds__(THREADS, 2)
gate_mma_kernel(const float* __restrict__ A1, const float* __restrict__ Wa, const float* __restrict__ ba,
                const float* __restrict__ A2, const float* __restrict__ Wb, const float* __restrict__ bb_,
                float* __restrict__ O, int Nrows)
{
    __shared__ float As[BK * SA];
    __shared__ float Bs[BK * SA];

    int tid  = threadIdx.x;
    int warp = tid >> 5;
    int lane = tid & 31;
    int g    = lane >> 2;   // groupID (0..7)
    int tig  = lane & 3;    // thread-in-group (0..3)
    int m_base = (warp >> 1) * 32;   // 0,32,64,96
    int n_base = (warp & 1) * 64;    // 0,64
    int row0 = blockIdx.x * 128;

    float acc[2][8][4];
#pragma unroll
    for (int mt = 0; mt < 2; ++mt)
#pragma unroll
        for (int nt = 0; nt < 8; ++nt)
#pragma unroll
            for (int i = 0; i < 4; ++i) acc[mt][nt][i] = 0.f;

#pragma unroll 1
    for (int pass = 0; pass < 2; ++pass) {
        const float* Ap = pass ? A2 : A1;
        const float* Wp = pass ? Wb : Wa;
#pragma unroll 1
        for (int kc = 0; kc < 8; ++kc) {
            load_As_tf(Ap, row0, Nrows, kc * BK, As, tid);
            load_Bs_tf(Wp, kc * BK, Bs, tid);
            __syncthreads();
#pragma unroll
            for (int ks = 0; ks < 2; ++ks) {
                int kk = ks * 8;
                // A fragments: a0=A[g][tig], a1=A[g+8][tig], a2=A[g][tig+4], a3=A[g+8][tig+4]
                uint32_t afr[2][4];
#pragma unroll
                for (int mt = 0; mt < 2; ++mt) {
                    int mr = m_base + mt * 16 + g;
                    afr[mt][0] = __float_as_uint(As[(kk + tig)     * SA + mr]);
                    afr[mt][1] = __float_as_uint(As[(kk + tig)     * SA + mr + 8]);
                    afr[mt][2] = __float_as_uint(As[(kk + tig + 4) * SA + mr]);
                    afr[mt][3] = __float_as_uint(As[(kk + tig + 4) * SA + mr + 8]);
                }
#pragma unroll
                for (int nt = 0; nt < 8; ++nt) {
                    int nc = n_base + nt * 8 + g;
                    uint32_t b0 = __float_as_uint(Bs[(kk + tig)     * SA + nc]);
                    uint32_t b1 = __float_as_uint(Bs[(kk + tig + 4) * SA + nc]);
                    mma_tf32(acc[0][nt], afr[0], b0, b1);
                    mma_tf32(acc[1][nt], afr[1], b0, b1);
                }
            }
            __syncthreads();
        }
    }

    // ---- epilogue: c0/c1 -> (row g, col 2tig/2tig+1), c2/c3 -> row g+8 ----
    const float2* x2 = reinterpret_cast<const float2*>(g_x);
    const float2* z2 = reinterpret_cast<const float2*>(g_z);
#pragma unroll
    for (int nt = 0; nt < 8; ++nt) {
        int col = n_base + nt * 8 + 2 * tig;
        float2 bsum;
        bsum.x = __ldg(&ba[col])     + __ldg(&bb_[col]);
        bsum.y = __ldg(&ba[col + 1]) + __ldg(&bb_[col + 1]);
#pragma unroll
        for (int mt = 0; mt < 2; ++mt) {
#pragma unroll
            for (int h = 0; h < 2; ++h) {
                int row = row0 + m_base + mt * 16 + g + h * 8;
                if (row >= Nrows) continue;
                float tx = acc[mt][nt][2 * h]     + bsum.x;
                float ty = acc[mt][nt][2 * h + 1] + bsum.y;
                size_t p = (size_t)row * 64 + (col >> 1);
                if (MODE == 0) {
                    reinterpret_cast<float2*>(g_z)[p] = make_float2(sigf(tx), sigf(ty));
                } else if (MODE == 1) {
                    float2 xv = x2[p];
                    reinterpret_cast<float2*>(g_rx)[p] =
                        make_float2(sigf(tx) * xv.x, sigf(ty) * xv.y);
                } else {
                    float2 xv = x2[p];
                    float2 zv = z2[p];
                    float2 o;
                    o.x = (1.f - zv.x) * xv.x + zv.x * tanhf(tx);
                    o.y = (1.f - zv.y) * xv.y + zv.y * tanhf(ty);
                    reinterpret_cast<float2*>(O)[p] = o;
                }
            }
        }
    }
}

// ===========================================================================
// Edge scatter: agg[rows[e]] += vals[e] * x[cols[e]]  (warp/edge, RED.v4)
// ===========================================================================
__device__ __forceinline__ void red4(float* p, float a, float b, float c, float d) {
    asm volatile("red.global.add.v4.f32 [%0], {%1, %2, %3, %4};"
                 :: "l"(p), "f"(a), "f"(b), "f"(c), "f"(d) : "memory");
}

__global__ void scatter_kernel(const int* __restrict__ rows, const int* __restrict__ cols,
                               const float* __restrict__ vals, const float* __restrict__ x,
                               float* __restrict__ agg, int E)
{
    int gw = (blockIdx.x * blockDim.x + threadIdx.x) >> 5;
    int lane = threadIdx.x & 31;
    int nw = (gridDim.x * blockDim.x) >> 5;
    const float4* x4 = reinterpret_cast<const float4*>(x);

    for (int e0 = gw * 2; e0 < E; e0 += nw * 2) {
        int e1 = e0 + 1;
        bool h1 = (e1 < E);
        int r0 = __ldg(&rows[e0]);
        int c0 = __ldg(&cols[e0]);
        float v0 = __ldg(&vals[e0]);
        int r1 = 0, c1 = 0;
        float v1 = 0.f;
        if (h1) { r1 = __ldg(&rows[e1]); c1 = __ldg(&cols[e1]); v1 = __ldg(&vals[e1]); }

        float4 a = x4[(size_t)c0 * D4 + lane];
        float4 b = h1 ? x4[(size_t)c1 * D4 + lane] : make_float4(0.f, 0.f, 0.f, 0.f);

        red4(agg + (size_t)r0 * D + lane * 4, v0 * a.x, v0 * a.y, v0 * a.z, v0 * a.w);
        if (h1)
            red4(agg + (size_t)r1 * D + lane * 4, v1 * b.x, v1 * b.y, v1 * b.z, v1 * b.w);
    }
}

__global__ void zero_kernel(float* __restrict__ p, int n4)
{
    int i = blockIdx.x * blockDim.x + threadIdx.x;
    if (i < n4) reinterpret_cast<float4*>(p)[i] = make_float4(0.f, 0.f, 0.f, 0.f);
}

// ---------------------------------------------------------------------------
extern "C" void kernel_launch(void* const* d_in, const int* in_sizes, int n_in,
                              void* d_out, int out_size)
{
    const float* x_in  = (const float*)d_in[0];
    const int*   rows  = (const int*)  d_in[1];
    const int*   cols  = (const int*)  d_in[2];
    const float* vals  = (const float*)d_in[3];
    const float* m1_W1 = (const float*)d_in[4];
    const float* m1_b1 = (const float*)d_in[5];
    const float* m1_W2 = (const float*)d_in[6];
    const float* m1_b2 = (const float*)d_in[7];
    const float* m2_W1 = (const float*)d_in[8];
    const float* m2_b1 = (const float*)d_in[9];
    const float* m2_W2 = (const float*)d_in[10];
    const float* m2_b2 = (const float*)d_in[11];
    const float* Wu1   = (const float*)d_in[12];
    const float* bu1   = (const float*)d_in[13];
    const float* Wu2   = (const float*)d_in[14];
    const float* bu2   = (const float*)d_in[15];
    const float* Wr1   = (const float*)d_in[16];
    const float* br1   = (const float*)d_in[17];
    const float* Wr2   = (const float*)d_in[18];
    const float* br2   = (const float*)d_in[19];
    const float* Wo1   = (const float*)d_in[20];
    const float* bo1   = (const float*)d_in[21];
    const float* Wo2   = (const float*)d_in[22];
    const float* bo2   = (const float*)d_in[23];

    int N = in_sizes[0] / D;
    int E = in_sizes[1];

    float *px, *pagg, *pout, *prx;
    cudaGetSymbolAddress((void**)&px,   g_x);
    cudaGetSymbolAddress((void**)&pagg, g_agg);
    cudaGetSymbolAddress((void**)&pout, g_out);
    cudaGetSymbolAddress((void**)&prx,  g_rx);

    int smem_mlp = (2 * BK * 128 + 128 * 128) * (int)sizeof(float);  // 80 KB
    cudaFuncSetAttribute(mlp2_kernel, cudaFuncAttributeMaxDynamicSharedMemorySize, smem_mlp);

    int nblk = (N + 127) / 128;
    int n4 = N * D / 4;

    zero_kernel<<<(n4 + 255) / 256, 256>>>(pagg, n4);
    mlp2_kernel<<<nblk, THREADS, smem_mlp>>>(x_in, m1_W1, m1_b1, m1_W2, m1_b2, px, N);
    scatter_kernel<<<2048, 256>>>(rows, cols, vals, px, pagg, E);
    mlp2_kernel<<<nblk, THREADS, smem_mlp>>>(pagg, m2_W1, m2_b1, m2_W2, m2_b2, pout, N);
    gate_mma_kernel<0><<<nblk, THREADS>>>(pout, Wu1, bu1, px, Wu2, bu2, nullptr, N);
    gate_mma_kernel<1><<<nblk, THREADS>>>(pout, Wr1, br1, px, Wr2, br2, nullptr, N);
    gate_mma_kernel<2><<<nblk, THREADS>>>(pout, Wo1, bo1, prx, Wo2, bo2, (float*)d_out, N);
}

// round 5
// speedup vs baseline: 2.5541x; 1.1919x over previous
#include <cuda_runtime.h>
#include <math.h>
#include <stdint.h>

#define D    128
#define D4   32
#define NMAX 50000
#define EMAX 1600000
#define BK   16
#define THREADS 256
#define SA   136   // smem row stride (floats): bank = (8*tig+g) -> conflict-free frags

// -------- device scratch (allocation-free rule: __device__ globals) --------
__device__ float g_x[NMAX * D];
__device__ float g_agg[NMAX * D];
__device__ float g_out[NMAX * D];
__device__ float g_z[NMAX * D];
__device__ float g_rx[NMAX * D];
__device__ int   g_cnt[NMAX];
__device__ int   g_start[NMAX + 1];
__device__ int   g_cur[NMAX];
__device__ int2  g_edges[EMAX];   // (col, val bits)

__device__ __forceinline__ float sigf(float x) { return 1.0f / (1.0f + expf(-x)); }

// ===========================================================================
// TF32 mma machinery (R4-proven).
// Block 128x128, 8 warps: warp grid 4(M) x 2(N); warp tile 32x64
//   = 2 m-tiles (m16) x 8 n-tiles (n8), 64 fp32 acc regs / thread.
// ===========================================================================

__device__ __forceinline__ uint32_t f2tf32(float f) {
    uint32_t u;
    asm("cvt.rna.tf32.f32 %0, %1;" : "=r"(u) : "f"(f));
    return u;
}

__device__ __forceinline__ void mma_tf32(float c[4], const uint32_t a[4],
                                         uint32_t b0, uint32_t b1) {
    asm volatile(
        "mma.sync.aligned.m16n8k8.row.col.f32.tf32.tf32.f32 "
        "{%0,%1,%2,%3}, {%4,%5,%6,%7}, {%8,%9}, {%0,%1,%2,%3};"
        : "+f"(c[0]), "+f"(c[1]), "+f"(c[2]), "+f"(c[3])
        : "r"(a[0]), "r"(a[1]), "r"(a[2]), "r"(a[3]), "r"(b0), "r"(b1));
}

// A chunk [row0..+128) x [k0..+16) transposed into As[k][row], tf32-rounded.
__device__ __forceinline__ void load_As_tf(const float* __restrict__ A, int row0,
                                           int Nrows, int k0, float* As, int tid) {
#pragma unroll
    for (int q = 0; q < 2; ++q) {
        int idx = tid + q * 256;
        int row = idx >> 2;
        int kq  = (idx & 3) << 2;
        float4 v = make_float4(0.f, 0.f, 0.f, 0.f);
        if (row0 + row < Nrows)
            v = reinterpret_cast<const float4*>(A)[(size_t)(row0 + row) * D4 + ((k0 + kq) >> 2)];
        As[(kq + 0) * SA + row] = __uint_as_float(f2tf32(v.x));
        As[(kq + 1) * SA + row] = __uint_as_float(f2tf32(v.y));
        As[(kq + 2) * SA + row] = __uint_as_float(f2tf32(v.z));
        As[(kq + 3) * SA + row] = __uint_as_float(f2tf32(v.w));
    }
}

// W chunk [k0..+16) x [0..128) into Bs[k][c] (k-major), tf32-rounded.
__device__ __forceinline__ void load_Bs_tf(const float* __restrict__ W, int k0,
                                           float* Bs, int tid) {
#pragma unroll
    for (int q = 0; q < 2; ++q) {
        int idx = tid + q * 256;
        int k  = idx >> 5;
        int c4 = idx & 31;
        float4 v = reinterpret_cast<const float4*>(W)[(size_t)(k0 + k) * D4 + c4];
        float4 t;
        t.x = __uint_as_float(f2tf32(v.x));
        t.y = __uint_as_float(f2tf32(v.y));
        t.z = __uint_as_float(f2tf32(v.z));
        t.w = __uint_as_float(f2tf32(v.w));
        *reinterpret_cast<float4*>(&Bs[k * SA + c4 * 4]) = t;
    }
}

// One 128-wide K-chunk pair of mma steps (ks=0,1) over the warp tile.
__device__ __forceinline__ void mma_chunk(const float* As, const float* Bs,
                                          int kk_a, int kk_b, int m_base, int n_base,
                                          int g, int tig, float acc[2][8][4]) {
#pragma unroll
    for (int ks = 0; ks < 2; ++ks) {
        int ka = kk_a + ks * 8;
        int kb = kk_b + ks * 8;
        uint32_t afr[2][4];
#pragma unroll
        for (int mt = 0; mt < 2; ++mt) {
            int mr = m_base + mt * 16 + g;
            afr[mt][0] = __float_as_uint(As[(ka + tig)     * SA + mr]);
            afr[mt][1] = __float_as_uint(As[(ka + tig)     * SA + mr + 8]);
            afr[mt][2] = __float_as_uint(As[(ka + tig + 4) * SA + mr]);
            afr[mt][3] = __float_as_uint(As[(ka + tig + 4) * SA + mr + 8]);
        }
#pragma unroll
        for (int nt = 0; nt < 8; ++nt) {
            int nc = n_base + nt * 8 + g;
            uint32_t b0 = __float_as_uint(Bs[(kb + tig)     * SA + nc]);
            uint32_t b1 = __float_as_uint(Bs[(kb + tig + 4) * SA + nc]);
            mma_tf32(acc[0][nt], afr[0], b0, b1);
            mma_tf32(acc[1][nt], afr[1], b0, b1);
        }
    }
}

// ===========================================================================
// Fused 2-layer MLP on tensor cores: O = relu(A@W1+b1)@W2 + b2  (tf32)
// H stored in SMEM as tf32 in [col][row] layout == A-fragment layout.
// ===========================================================================
__global__ void __launch_bounds__(THREADS, 2)
mlp2_mma_kernel(const float* __restrict__ A,
                const float* __restrict__ W1, const float* __restrict__ b1,
                const float* __restrict__ W2, const float* __restrict__ b2,
                float* __restrict__ O, int Nrows)
{
    extern __shared__ float sm[];
    float* As = sm;                 // 16*SA
    float* Bs = sm + BK * SA;       // 16*SA
    float* Hs = sm + 2 * BK * SA;   // 128*SA

    int tid  = threadIdx.x;
    int warp = tid >> 5;
    int lane = tid & 31;
    int g    = lane >> 2;
    int tig  = lane & 3;
    int m_base = (warp >> 1) * 32;
    int n_base = (warp & 1) * 64;
    int row0 = blockIdx.x * 128;

    float acc[2][8][4];
#pragma unroll
    for (int mt = 0; mt < 2; ++mt)
#pragma unroll
        for (int nt = 0; nt < 8; ++nt)
#pragma unroll
            for (int i = 0; i < 4; ++i) acc[mt][nt][i] = 0.f;

    // ---- layer 1: A @ W1 ----
#pragma unroll 1
    for (int kc = 0; kc < 8; ++kc) {
        load_As_tf(A, row0, Nrows, kc * BK, As, tid);
        load_Bs_tf(W1, kc * BK, Bs, tid);
        __syncthreads();
        mma_chunk(As, Bs, 0, 0, m_base, n_base, g, tig, acc);
        __syncthreads();
    }

    // ---- epilogue 1: relu(acc + b1) -> Hs[col][row] (tf32) ----
#pragma unroll
    for (int nt = 0; nt < 8; ++nt) {
        int col = n_base + nt * 8 + 2 * tig;
        float bx = __ldg(&b1[col]);
        float by = __ldg(&b1[col + 1]);
#pragma unroll
        for (int mt = 0; mt < 2; ++mt) {
#pragma unroll
            for (int h = 0; h < 2; ++h) {
                int row = m_base + mt * 16 + g + h * 8;
                float tx = fmaxf(acc[mt][nt][2 * h]     + bx, 0.f);
                float ty = fmaxf(acc[mt][nt][2 * h + 1] + by, 0.f);
                Hs[col * SA + row]       = __uint_as_float(f2tf32(tx));
                Hs[(col + 1) * SA + row] = __uint_as_float(f2tf32(ty));
                acc[mt][nt][2 * h] = 0.f;
                acc[mt][nt][2 * h + 1] = 0.f;
            }
        }
    }
    __syncthreads();

    // ---- layer 2: Hs @ W2 ----
#pragma unroll 1
    for (int kc = 0; kc < 8; ++kc) {
        load_Bs_tf(W2, kc * BK, Bs, tid);
        __syncthreads();
        mma_chunk(Hs, Bs, kc * BK, 0, m_base, n_base, g, tig, acc);
        __syncthreads();
    }

    // ---- epilogue 2: O = acc + b2 ----
#pragma unroll
    for (int nt = 0; nt < 8; ++nt) {
        int col = n_base + nt * 8 + 2 * tig;
        float2 bb = make_float2(__ldg(&b2[col]), __ldg(&b2[col + 1]));
#pragma unroll
        for (int mt = 0; mt < 2; ++mt) {
#pragma unroll
            for (int h = 0; h < 2; ++h) {
                int row = row0 + m_base + mt * 16 + g + h * 8;
                if (row >= Nrows) continue;
                float2 o = make_float2(acc[mt][nt][2 * h] + bb.x,
                                       acc[mt][nt][2 * h + 1] + bb.y);
                *reinterpret_cast<float2*>(&O[(size_t)row * D + col]) = o;
            }
        }
    }
}

// ===========================================================================
// TF32 gate kernels (R4-proven): acc = A1@Wa + A2@Wb, mode epilogue.
// ===========================================================================
template <int MODE>
__global__ void __launch_bounds__(THREADS, 2)
gate_mma_kernel(const float* __restrict__ A1, const float* __restrict__ Wa, const float* __restrict__ ba,
                const float* __restrict__ A2, const float* __restrict__ Wb, const float* __restrict__ bb_,
                float* __restrict__ O, int Nrows)
{
    __shared__ float As[BK * SA];
    __shared__ float Bs[BK * SA];

    int tid  = threadIdx.x;
    int warp = tid >> 5;
    int lane = tid & 31;
    int g    = lane >> 2;
    int tig  = lane & 3;
    int m_base = (warp >> 1) * 32;
    int n_base = (warp & 1) * 64;
    int row0 = blockIdx.x * 128;

    float acc[2][8][4];
#pragma unroll
    for (int mt = 0; mt < 2; ++mt)
#pragma unroll
        for (int nt = 0; nt < 8; ++nt)
#pragma unroll
            for (int i = 0; i < 4; ++i) acc[mt][nt][i] = 0.f;

#pragma unroll 1
    for (int pass = 0; pass < 2; ++pass) {
        const float* Ap = pass ? A2 : A1;
        const float* Wp = pass ? Wb : Wa;
#pragma unroll 1
        for (int kc = 0; kc < 8; ++kc) {
            load_As_tf(Ap, row0, Nrows, kc * BK, As, tid);
            load_Bs_tf(Wp, kc * BK, Bs, tid);
            __syncthreads();
            mma_chunk(As, Bs, 0, 0, m_base, n_base, g, tig, acc);
            __syncthreads();
        }
    }

    const float2* x2 = reinterpret_cast<const float2*>(g_x);
    const float2* z2 = reinterpret_cast<const float2*>(g_z);
#pragma unroll
    for (int nt = 0; nt < 8; ++nt) {
        int col = n_base + nt * 8 + 2 * tig;
        float2 bsum;
        bsum.x = __ldg(&ba[col])     + __ldg(&bb_[col]);
        bsum.y = __ldg(&ba[col + 1]) + __ldg(&bb_[col + 1]);
#pragma unroll
        for (int mt = 0; mt < 2; ++mt) {
#pragma unroll
            for (int h = 0; h < 2; ++h) {
                int row = row0 + m_base + mt * 16 + g + h * 8;
                if (row >= Nrows) continue;
                float tx = acc[mt][nt][2 * h]     + bsum.x;
                float ty = acc[mt][nt][2 * h + 1] + bsum.y;
                size_t p = (size_t)row * 64 + (col >> 1);
                if (MODE == 0) {
                    reinterpret_cast<float2*>(g_z)[p] = make_float2(sigf(tx), sigf(ty));
                } else if (MODE == 1) {
                    float2 xv = x2[p];
                    reinterpret_cast<float2*>(g_rx)[p] =
                        make_float2(sigf(tx) * xv.x, sigf(ty) * xv.y);
                } else {
                    float2 xv = x2[p];
                    float2 zv = z2[p];
                    float2 o;
                    o.x = (1.f - zv.x) * xv.x + zv.x * tanhf(tx);
                    o.y = (1.f - zv.y) * xv.y + zv.y * tanhf(ty);
                    reinterpret_cast<float2*>(O)[p] = o;
                }
            }
        }
    }
}

// ===========================================================================
// CSR build + atomic-free aggregation
// ===========================================================================
__global__ void zero_cnt_kernel(int Nn)
{
    int i = blockIdx.x * blockDim.x + threadIdx.x;
    if (i < Nn) g_cnt[i] = 0;
}

__global__ void count_kernel(const int* __restrict__ rows, int E)
{
    int e = blockIdx.x * blockDim.x + threadIdx.x;
    if (e < E) atomicAdd(&g_cnt[rows[e]], 1);
}

// Single-block exclusive scan over g_cnt -> g_start (+ copy to g_cur).
__global__ void scan_kernel(int Nn)
{
    __shared__ int warp_tot[32];
    int t = threadIdx.x;                  // 1024 threads
    int lane = t & 31, w = t >> 5;
    int C = (Nn + 1023) / 1024;
    int lo = t * C;
    int hi = min(lo + C, Nn);

    int sum = 0;
    for (int i = lo; i < hi; ++i) sum += g_cnt[i];

    // inclusive warp scan
    int v = sum;
#pragma unroll
    for (int o = 1; o < 32; o <<= 1) {
        int u = __shfl_up_sync(0xffffffffu, v, o);
        if (lane >= o) v += u;
    }
    if (lane == 31) warp_tot[w] = v;
    __syncthreads();
    if (w == 0) {
        int tv = warp_tot[lane];
#pragma unroll
        for (int o = 1; o < 32; o <<= 1) {
            int u = __shfl_up_sync(0xffffffffu, tv, o);
            if (lane >= o) tv += u;
        }
        warp_tot[lane] = tv;
    }
    __syncthreads();
    int incl = v + (w > 0 ? warp_tot[w - 1] : 0);
    int run = incl - sum;                 // exclusive prefix at lo

    for (int i = lo; i < hi; ++i) {
        int c = g_cnt[i];
        g_start[i] = run;
        g_cur[i] = run;
        run += c;
    }
    if (t == 1023) g_start[Nn] = run;     // total E
}

__global__ void fill_kernel(const int* __restrict__ rows, const int* __restrict__ cols,
                            const float* __restrict__ vals, int E)
{
    int e = blockIdx.x * blockDim.x + threadIdx.x;
    if (e < E) {
        int r = rows[e];
        int pos = atomicAdd(&g_cur[r], 1);
        g_edges[pos] = make_int2(cols[e], __float_as_int(vals[e]));
    }
}

// Warp per node: agg[i] = sum_j val_j * x[col_j], no atomics.
__global__ void agg_kernel(const float* __restrict__ x, float* __restrict__ agg, int Nn)
{
    int gw = (blockIdx.x * blockDim.x + threadIdx.x) >> 5;
    int lane = threadIdx.x & 31;
    if (gw >= Nn) return;

    int s = __ldg(&g_start[gw]);
    int t = __ldg(&g_start[gw + 1]);
    const float4* x4 = reinterpret_cast<const float4*>(x);

    float4 acc = make_float4(0.f, 0.f, 0.f, 0.f);
    int j = s;
    for (; j + 2 <= t; j += 2) {
        int2 ea = __ldg(&g_edges[j]);
        int2 eb = __ldg(&g_edges[j + 1]);
        float4 xa = x4[(size_t)ea.x * D4 + lane];
        float4 xb = x4[(size_t)eb.x * D4 + lane];
        float va = __int_as_float(ea.y);
        float vb = __int_as_float(eb.y);
        acc.x += va * xa.x; acc.y += va * xa.y; acc.z += va * xa.z; acc.w += va * xa.w;
        acc.x += vb * xb.x; acc.y += vb * xb.y; acc.z += vb * xb.z; acc.w += vb * xb.w;
    }
    if (j < t) {
        int2 ea = __ldg(&g_edges[j]);
        float4 xa = x4[(size_t)ea.x * D4 + lane];
        float va = __int_as_float(ea.y);
        acc.x += va * xa.x; acc.y += va * xa.y; acc.z += va * xa.z; acc.w += va * xa.w;
    }
    reinterpret_cast<float4*>(agg)[(size_t)gw * D4 + lane] = acc;
}

// ---------------------------------------------------------------------------
extern "C" void kernel_launch(void* const* d_in, const int* in_sizes, int n_in,
                              void* d_out, int out_size)
{
    const float* x_in  = (const float*)d_in[0];
    const int*   rows  = (const int*)  d_in[1];
    const int*   cols  = (const int*)  d_in[2];
    const float* vals  = (const float*)d_in[3];
    const float* m1_W1 = (const float*)d_in[4];
    const float* m1_b1 = (const float*)d_in[5];
    const float* m1_W2 = (const float*)d_in[6];
    const float* m1_b2 = (const float*)d_in[7];
    const float* m2_W1 = (const float*)d_in[8];
    const float* m2_b1 = (const float*)d_in[9];
    const float* m2_W2 = (const float*)d_in[10];
    const float* m2_b2 = (const float*)d_in[11];
    const float* Wu1   = (const float*)d_in[12];
    const float* bu1   = (const float*)d_in[13];
    const float* Wu2   = (const float*)d_in[14];
    const float* bu2   = (const float*)d_in[15];
    const float* Wr1   = (const float*)d_in[16];
    const float* br1   = (const float*)d_in[17];
    const float* Wr2   = (const float*)d_in[18];
    const float* br2   = (const float*)d_in[19];
    const float* Wo1   = (const float*)d_in[20];
    const float* bo1   = (const float*)d_in[21];
    const float* Wo2   = (const float*)d_in[22];
    const float* bo2   = (const float*)d_in[23];

    int N = in_sizes[0] / D;
    int E = in_sizes[1];

    float *px, *pagg, *pout, *prx;
    cudaGetSymbolAddress((void**)&px,   g_x);
    cudaGetSymbolAddress((void**)&pagg, g_agg);
    cudaGetSymbolAddress((void**)&pout, g_out);
    cudaGetSymbolAddress((void**)&prx,  g_rx);

    int smem_mlp = (2 * BK * SA + 128 * SA) * (int)sizeof(float);  // 87040 B
    cudaFuncSetAttribute(mlp2_mma_kernel, cudaFuncAttributeMaxDynamicSharedMemorySize, smem_mlp);

    int nblk = (N + 127) / 128;
    int eblk = (E + 255) / 256;

    // CSR build (independent of x)
    zero_cnt_kernel<<<(N + 255) / 256, 256>>>(N);
    count_kernel<<<eblk, 256>>>(rows, E);
    scan_kernel<<<1, 1024>>>(N);
    fill_kernel<<<eblk, 256>>>(rows, cols, vals, E);

    // x = mlp1(x_in)
    mlp2_mma_kernel<<<nblk, THREADS, smem_mlp>>>(x_in, m1_W1, m1_b1, m1_W2, m1_b2, px, N);

    // agg = segment_sum(vals * x[cols]) by rows  (atomic-free gather)
    agg_kernel<<<(N * 32 + 255) / 256, 256>>>(px, pagg, N);

    // out = mlp2(agg)
    mlp2_mma_kernel<<<nblk, THREADS, smem_mlp>>>(pagg, m2_W1, m2_b1, m2_W2, m2_b2, pout, N);

    // gates
    gate_mma_kernel<0><<<nblk, THREADS>>>(pout, Wu1, bu1, px, Wu2, bu2, nullptr, N);
    gate_mma_kernel<1><<<nblk, THREADS>>>(pout, Wr1, br1, px, Wr2, br2, nullptr, N);
    gate_mma_kernel<2><<<nblk, THREADS>>>(pout, Wo1, bo1, prx, Wo2, bo2, (float*)d_out, N);
}

// round 6
// speedup vs baseline: 2.5729x; 1.0073x over previous
#include <cuda_runtime.h>
#include <math.h>
#include <stdint.h>

#define D    128
#define D4   32
#define NMAX 50000
#define EMAX 1600000
#define BK   16
#define THREADS 256
#define SA   136   // smem row stride (floats): bank = (8*tig+g) -> conflict-free frags

// -------- device scratch (allocation-free rule: __device__ globals) --------
__device__ float g_x[NMAX * D];
__device__ float g_agg[NMAX * D];
__device__ float g_out[NMAX * D];
__device__ float g_z[NMAX * D];
__device__ float g_rx[NMAX * D];
__device__ int   g_cnt[NMAX];
__device__ int   g_start[NMAX + 1];
__device__ int   g_cur[NMAX];
__device__ int2  g_edges[EMAX];   // (col, val bits)

__device__ __forceinline__ float sigf(float x) { return 1.0f / (1.0f + expf(-x)); }

// ===========================================================================
// TF32 mma machinery (R4/R5-proven).
// ===========================================================================

__device__ __forceinline__ uint32_t f2tf32(float f) {
    uint32_t u;
    asm("cvt.rna.tf32.f32 %0, %1;" : "=r"(u) : "f"(f));
    return u;
}

__device__ __forceinline__ void mma_tf32(float c[4], const uint32_t a[4],
                                         uint32_t b0, uint32_t b1) {
    asm volatile(
        "mma.sync.aligned.m16n8k8.row.col.f32.tf32.tf32.f32 "
        "{%0,%1,%2,%3}, {%4,%5,%6,%7}, {%8,%9}, {%0,%1,%2,%3};"
        : "+f"(c[0]), "+f"(c[1]), "+f"(c[2]), "+f"(c[3])
        : "r"(a[0]), "r"(a[1]), "r"(a[2]), "r"(a[3]), "r"(b0), "r"(b1));
}

__device__ __forceinline__ void load_As_tf(const float* __restrict__ A, int row0,
                                           int Nrows, int k0, float* As, int tid) {
#pragma unroll
    for (int q = 0; q < 2; ++q) {
        int idx = tid + q * 256;
        int row = idx >> 2;
        int kq  = (idx & 3) << 2;
        float4 v = make_float4(0.f, 0.f, 0.f, 0.f);
        if (row0 + row < Nrows)
            v = reinterpret_cast<const float4*>(A)[(size_t)(row0 + row) * D4 + ((k0 + kq) >> 2)];
        As[(kq + 0) * SA + row] = __uint_as_float(f2tf32(v.x));
        As[(kq + 1) * SA + row] = __uint_as_float(f2tf32(v.y));
        As[(kq + 2) * SA + row] = __uint_as_float(f2tf32(v.z));
        As[(kq + 3) * SA + row] = __uint_as_float(f2tf32(v.w));
    }
}

__device__ __forceinline__ void load_Bs_tf(const float* __restrict__ W, int k0,
                                           float* Bs, int tid) {
#pragma unroll
    for (int q = 0; q < 2; ++q) {
        int idx = tid + q * 256;
        int k  = idx >> 5;
        int c4 = idx & 31;
        float4 v = reinterpret_cast<const float4*>(W)[(size_t)(k0 + k) * D4 + c4];
        float4 t;
        t.x = __uint_as_float(f2tf32(v.x));
        t.y = __uint_as_float(f2tf32(v.y));
        t.z = __uint_as_float(f2tf32(v.z));
        t.w = __uint_as_float(f2tf32(v.w));
        *reinterpret_cast<float4*>(&Bs[k * SA + c4 * 4]) = t;
    }
}

__device__ __forceinline__ void mma_chunk(const float* As, const float* Bs,
                                          int kk_a, int kk_b, int m_base, int n_base,
                                          int g, int tig, float acc[2][8][4]) {
#pragma unroll
    for (int ks = 0; ks < 2; ++ks) {
        int ka = kk_a + ks * 8;
        int kb = kk_b + ks * 8;
        uint32_t afr[2][4];
#pragma unroll
        for (int mt = 0; mt < 2; ++mt) {
            int mr = m_base + mt * 16 + g;
            afr[mt][0] = __float_as_uint(As[(ka + tig)     * SA + mr]);
            afr[mt][1] = __float_as_uint(As[(ka + tig)     * SA + mr + 8]);
            afr[mt][2] = __float_as_uint(As[(ka + tig + 4) * SA + mr]);
            afr[mt][3] = __float_as_uint(As[(ka + tig + 4) * SA + mr + 8]);
        }
#pragma unroll
        for (int nt = 0; nt < 8; ++nt) {
            int nc = n_base + nt * 8 + g;
            uint32_t b0 = __float_as_uint(Bs[(kb + tig)     * SA + nc]);
            uint32_t b1 = __float_as_uint(Bs[(kb + tig + 4) * SA + nc]);
            mma_tf32(acc[0][nt], afr[0], b0, b1);
            mma_tf32(acc[1][nt], afr[1], b0, b1);
        }
    }
}

// ===========================================================================
// Fused 2-layer MLP on tensor cores (R5-proven).
// ===========================================================================
__global__ void __launch_bounds__(THREADS, 2)
mlp2_mma_kernel(const float* __restrict__ A,
                const float* __restrict__ W1, const float* __restrict__ b1,
                const float* __restrict__ W2, const float* __restrict__ b2,
                float* __restrict__ O, int Nrows)
{
    extern __shared__ float sm[];
    float* As = sm;
    float* Bs = sm + BK * SA;
    float* Hs = sm + 2 * BK * SA;

    int tid  = threadIdx.x;
    int warp = tid >> 5;
    int lane = tid & 31;
    int g    = lane >> 2;
    int tig  = lane & 3;
    int m_base = (warp >> 1) * 32;
    int n_base = (warp & 1) * 64;
    int row0 = blockIdx.x * 128;

    float acc[2][8][4];
#pragma unroll
    for (int mt = 0; mt < 2; ++mt)
#pragma unroll
        for (int nt = 0; nt < 8; ++nt)
#pragma unroll
            for (int i = 0; i < 4; ++i) acc[mt][nt][i] = 0.f;

#pragma unroll 1
    for (int kc = 0; kc < 8; ++kc) {
        load_As_tf(A, row0, Nrows, kc * BK, As, tid);
        load_Bs_tf(W1, kc * BK, Bs, tid);
        __syncthreads();
        mma_chunk(As, Bs, 0, 0, m_base, n_base, g, tig, acc);
        __syncthreads();
    }

#pragma unroll
    for (int nt = 0; nt < 8; ++nt) {
        int col = n_base + nt * 8 + 2 * tig;
        float bx = __ldg(&b1[col]);
        float by = __ldg(&b1[col + 1]);
#pragma unroll
        for (int mt = 0; mt < 2; ++mt) {
#pragma unroll
            for (int h = 0; h < 2; ++h) {
                int row = m_base + mt * 16 + g + h * 8;
                float tx = fmaxf(acc[mt][nt][2 * h]     + bx, 0.f);
                float ty = fmaxf(acc[mt][nt][2 * h + 1] + by, 0.f);
                Hs[col * SA + row]       = __uint_as_float(f2tf32(tx));
                Hs[(col + 1) * SA + row] = __uint_as_float(f2tf32(ty));
                acc[mt][nt][2 * h] = 0.f;
                acc[mt][nt][2 * h + 1] = 0.f;
            }
        }
    }
    __syncthreads();

#pragma unroll 1
    for (int kc = 0; kc < 8; ++kc) {
        load_Bs_tf(W2, kc * BK, Bs, tid);
        __syncthreads();
        mma_chunk(Hs, Bs, kc * BK, 0, m_base, n_base, g, tig, acc);
        __syncthreads();
    }

#pragma unroll
    for (int nt = 0; nt < 8; ++nt) {
        int col = n_base + nt * 8 + 2 * tig;
        float2 bb = make_float2(__ldg(&b2[col]), __ldg(&b2[col + 1]));
#pragma unroll
        for (int mt = 0; mt < 2; ++mt) {
#pragma unroll
            for (int h = 0; h < 2; ++h) {
                int row = row0 + m_base + mt * 16 + g + h * 8;
                if (row >= Nrows) continue;
                float2 o = make_float2(acc[mt][nt][2 * h] + bb.x,
                                       acc[mt][nt][2 * h + 1] + bb.y);
                *reinterpret_cast<float2*>(&O[(size_t)row * D + col]) = o;
            }
        }
    }
}

// ===========================================================================
// Merged z/r gate kernel: gridDim.y = 2.
//   y==0: g_z  = sigmoid(out@Wu1 + x@Wu2 + bu1 + bu2)
//   y==1: g_rx = sigmoid(out@Wr1 + x@Wr2 + br1 + br2) * g_x
// One contiguous wave schedule instead of two kernel tails.
// ===========================================================================
__global__ void __launch_bounds__(THREADS, 2)
gate01_mma_kernel(const float* __restrict__ out_, const float* __restrict__ x_,
                  const float* __restrict__ Wu1, const float* __restrict__ bu1,
                  const float* __restrict__ Wu2, const float* __restrict__ bu2,
                  const float* __restrict__ Wr1, const float* __restrict__ br1,
                  const float* __restrict__ Wr2, const float* __restrict__ br2,
                  int Nrows)
{
    __shared__ float As[BK * SA];
    __shared__ float Bs[BK * SA];

    int mode = blockIdx.y;
    const float* Wa = mode ? Wr1 : Wu1;
    const float* Wb = mode ? Wr2 : Wu2;
    const float* ba = mode ? br1 : bu1;
    const float* bb_ = mode ? br2 : bu2;

    int tid  = threadIdx.x;
    int warp = tid >> 5;
    int lane = tid & 31;
    int g    = lane >> 2;
    int tig  = lane & 3;
    int m_base = (warp >> 1) * 32;
    int n_base = (warp & 1) * 64;
    int row0 = blockIdx.x * 128;

    float acc[2][8][4];
#pragma unroll
    for (int mt = 0; mt < 2; ++mt)
#pragma unroll
        for (int nt = 0; nt < 8; ++nt)
#pragma unroll
            for (int i = 0; i < 4; ++i) acc[mt][nt][i] = 0.f;

#pragma unroll 1
    for (int pass = 0; pass < 2; ++pass) {
        const float* Ap = pass ? x_ : out_;
        const float* Wp = pass ? Wb : Wa;
#pragma unroll 1
        for (int kc = 0; kc < 8; ++kc) {
            load_As_tf(Ap, row0, Nrows, kc * BK, As, tid);
            load_Bs_tf(Wp, kc * BK, Bs, tid);
            __syncthreads();
            mma_chunk(As, Bs, 0, 0, m_base, n_base, g, tig, acc);
            __syncthreads();
        }
    }

    const float2* x2 = reinterpret_cast<const float2*>(g_x);
#pragma unroll
    for (int nt = 0; nt < 8; ++nt) {
        int col = n_base + nt * 8 + 2 * tig;
        float2 bsum;
        bsum.x = __ldg(&ba[col])     + __ldg(&bb_[col]);
        bsum.y = __ldg(&ba[col + 1]) + __ldg(&bb_[col + 1]);
#pragma unroll
        for (int mt = 0; mt < 2; ++mt) {
#pragma unroll
            for (int h = 0; h < 2; ++h) {
                int row = row0 + m_base + mt * 16 + g + h * 8;
                if (row >= Nrows) continue;
                float sx = sigf(acc[mt][nt][2 * h]     + bsum.x);
                float sy = sigf(acc[mt][nt][2 * h + 1] + bsum.y);
                size_t p = (size_t)row * 64 + (col >> 1);
                if (mode == 0) {
                    reinterpret_cast<float2*>(g_z)[p] = make_float2(sx, sy);
                } else {
                    float2 xv = x2[p];
                    reinterpret_cast<float2*>(g_rx)[p] = make_float2(sx * xv.x, sy * xv.y);
                }
            }
        }
    }
}

// Final gate: O = (1-z)*x + z*tanh(out@Wo1 + rx@Wo2 + bo1 + bo2)
__global__ void __launch_bounds__(THREADS, 2)
gate2_mma_kernel(const float* __restrict__ out_, const float* __restrict__ Wo1, const float* __restrict__ bo1,
                 const float* __restrict__ rx_, const float* __restrict__ Wo2, const float* __restrict__ bo2,
                 float* __restrict__ O, int Nrows)
{
    __shared__ float As[BK * SA];
    __shared__ float Bs[BK * SA];

    int tid  = threadIdx.x;
    int warp = tid >> 5;
    int lane = tid & 31;
    int g    = lane >> 2;
    int tig  = lane & 3;
    int m_base = (warp >> 1) * 32;
    int n_base = (warp & 1) * 64;
    int row0 = blockIdx.x * 128;

    float acc[2][8][4];
#pragma unroll
    for (int mt = 0; mt < 2; ++mt)
#pragma unroll
        for (int nt = 0; nt < 8; ++nt)
#pragma unroll
            for (int i = 0; i < 4; ++i) acc[mt][nt][i] = 0.f;

#pragma unroll 1
    for (int pass = 0; pass < 2; ++pass) {
        const float* Ap = pass ? rx_ : out_;
        const float* Wp = pass ? Wo2 : Wo1;
#pragma unroll 1
        for (int kc = 0; kc < 8; ++kc) {
            load_As_tf(Ap, row0, Nrows, kc * BK, As, tid);
            load_Bs_tf(Wp, kc * BK, Bs, tid);
            __syncthreads();
            mma_chunk(As, Bs, 0, 0, m_base, n_base, g, tig, acc);
            __syncthreads();
        }
    }

    const float2* x2 = reinterpret_cast<const float2*>(g_x);
    const float2* z2 = reinterpret_cast<const float2*>(g_z);
#pragma unroll
    for (int nt = 0; nt < 8; ++nt) {
        int col = n_base + nt * 8 + 2 * tig;
        float2 bsum;
        bsum.x = __ldg(&bo1[col])     + __ldg(&bo2[col]);
        bsum.y = __ldg(&bo1[col + 1]) + __ldg(&bo2[col + 1]);
#pragma unroll
        for (int mt = 0; mt < 2; ++mt) {
#pragma unroll
            for (int h = 0; h < 2; ++h) {
                int row = row0 + m_base + mt * 16 + g + h * 8;
                if (row >= Nrows) continue;
                float tx = acc[mt][nt][2 * h]     + bsum.x;
                float ty = acc[mt][nt][2 * h + 1] + bsum.y;
                size_t p = (size_t)row * 64 + (col >> 1);
                float2 xv = x2[p];
                float2 zv = z2[p];
                float2 o;
                o.x = (1.f - zv.x) * xv.x + zv.x * tanhf(tx);
                o.y = (1.f - zv.y) * xv.y + zv.y * tanhf(ty);
                reinterpret_cast<float2*>(O)[p] = o;
            }
        }
    }
}

// ===========================================================================
// CSR build + atomic-free aggregation
// ===========================================================================
__global__ void zero_cnt_kernel(int Nn)
{
    int i = blockIdx.x * blockDim.x + threadIdx.x;
    if (i < Nn) g_cnt[i] = 0;
}

__global__ void count_kernel(const int* __restrict__ rows, int E)
{
    int e = blockIdx.x * blockDim.x + threadIdx.x;
    if (e < E) atomicAdd(&g_cnt[rows[e]], 1);
}

__global__ void scan_kernel(int Nn)
{
    __shared__ int warp_tot[32];
    int t = threadIdx.x;                  // 1024 threads
    int lane = t & 31, w = t >> 5;
    int C = (Nn + 1023) / 1024;
    int lo = t * C;
    int hi = min(lo + C, Nn);

    int sum = 0;
    for (int i = lo; i < hi; ++i) sum += g_cnt[i];

    int v = sum;
#pragma unroll
    for (int o = 1; o < 32; o <<= 1) {
        int u = __shfl_up_sync(0xffffffffu, v, o);
        if (lane >= o) v += u;
    }
    if (lane == 31) warp_tot[w] = v;
    __syncthreads();
    if (w == 0) {
        int tv = warp_tot[lane];
#pragma unroll
        for (int o = 1; o < 32; o <<= 1) {
            int u = __shfl_up_sync(0xffffffffu, tv, o);
            if (lane >= o) tv += u;
        }
        warp_tot[lane] = tv;
    }
    __syncthreads();
    int incl = v + (w > 0 ? warp_tot[w - 1] : 0);
    int run = incl - sum;

    for (int i = lo; i < hi; ++i) {
        int c = g_cnt[i];
        g_start[i] = run;
        g_cur[i] = run;
        run += c;
    }
    if (t == 1023) g_start[Nn] = run;
}

// 2 independent atomic-ticket chains per thread (latency hiding), coalesced.
__global__ void fill_kernel(const int* __restrict__ rows, const int* __restrict__ cols,
                            const float* __restrict__ vals, int E)
{
    int base = blockIdx.x * 512;
    int e0 = base + threadIdx.x;
    int e1 = e0 + 256;
    if (e0 < E) {
        int r0 = rows[e0];
        int c0 = cols[e0];
        float v0 = vals[e0];
        int r1 = -1, c1 = 0; float v1 = 0.f;
        if (e1 < E) { r1 = rows[e1]; c1 = cols[e1]; v1 = vals[e1]; }
        int p0 = atomicAdd(&g_cur[r0], 1);
        int p1 = (r1 >= 0) ? atomicAdd(&g_cur[r1], 1) : 0;
        g_edges[p0] = make_int2(c0, __float_as_int(v0));
        if (r1 >= 0) g_edges[p1] = make_int2(c1, __float_as_int(v1));
    }
}

// Warp per node: agg[i] = sum_j val_j * x[col_j], no atomics.
__global__ void agg_kernel(const float* __restrict__ x, float* __restrict__ agg, int Nn)
{
    int gw = (blockIdx.x * blockDim.x + threadIdx.x) >> 5;
    int lane = threadIdx.x & 31;
    if (gw >= Nn) return;

    int s = __ldg(&g_start[gw]);
    int t = __ldg(&g_start[gw + 1]);
    const float4* x4 = reinterpret_cast<const float4*>(x);

    float4 acc = make_float4(0.f, 0.f, 0.f, 0.f);
    int j = s;
    for (; j + 2 <= t; j += 2) {
        int2 ea = __ldg(&g_edges[j]);
        int2 eb = __ldg(&g_edges[j + 1]);
        float4 xa = x4[(size_t)ea.x * D4 + lane];
        float4 xb = x4[(size_t)eb.x * D4 + lane];
        float va = __int_as_float(ea.y);
        float vb = __int_as_float(eb.y);
        acc.x += va * xa.x; acc.y += va * xa.y; acc.z += va * xa.z; acc.w += va * xa.w;
        acc.x += vb * xb.x; acc.y += vb * xb.y; acc.z += vb * xb.z; acc.w += vb * xb.w;
    }
    if (j < t) {
        int2 ea = __ldg(&g_edges[j]);
        float4 xa = x4[(size_t)ea.x * D4 + lane];
        float va = __int_as_float(ea.y);
        acc.x += va * xa.x; acc.y += va * xa.y; acc.z += va * xa.z; acc.w += va * xa.w;
    }
    reinterpret_cast<float4*>(agg)[(size_t)gw * D4 + lane] = acc;
}

// ---------------------------------------------------------------------------
extern "C" void kernel_launch(void* const* d_in, const int* in_sizes, int n_in,
                              void* d_out, int out_size)
{
    const float* x_in  = (const float*)d_in[0];
    const int*   rows  = (const int*)  d_in[1];
    const int*   cols  = (const int*)  d_in[2];
    const float* vals  = (const float*)d_in[3];
    const float* m1_W1 = (const float*)d_in[4];
    const float* m1_b1 = (const float*)d_in[5];
    const float* m1_W2 = (const float*)d_in[6];
    const float* m1_b2 = (const float*)d_in[7];
    const float* m2_W1 = (const float*)d_in[8];
    const float* m2_b1 = (const float*)d_in[9];
    const float* m2_W2 = (const float*)d_in[10];
    const float* m2_b2 = (const float*)d_in[11];
    const float* Wu1   = (const float*)d_in[12];
    const float* bu1   = (const float*)d_in[13];
    const float* Wu2   = (const float*)d_in[14];
    const float* bu2   = (const float*)d_in[15];
    const float* Wr1   = (const float*)d_in[16];
    const float* br1   = (const float*)d_in[17];
    const float* Wr2   = (const float*)d_in[18];
    const float* br2   = (const float*)d_in[19];
    const float* Wo1   = (const float*)d_in[20];
    const float* bo1   = (const float*)d_in[21];
    const float* Wo2   = (const float*)d_in[22];
    const float* bo2   = (const float*)d_in[23];

    int N = in_sizes[0] / D;
    int E = in_sizes[1];

    float *px, *pagg, *pout, *prx;
    cudaGetSymbolAddress((void**)&px,   g_x);
    cudaGetSymbolAddress((void**)&pagg, g_agg);
    cudaGetSymbolAddress((void**)&pout, g_out);
    cudaGetSymbolAddress((void**)&prx,  g_rx);

    // One-time side stream + events (host resources only; enqueued work is
    // identical on every call, so determinism holds).
    static cudaStream_t s_side = nullptr;
    static cudaEvent_t ev_fork = nullptr, ev_join = nullptr;
    if (!s_side) {
        cudaStreamCreateWithFlags(&s_side, cudaStreamNonBlocking);
        cudaEventCreateWithFlags(&ev_fork, cudaEventDisableTiming);
        cudaEventCreateWithFlags(&ev_join, cudaEventDisableTiming);
    }

    int smem_mlp = (2 * BK * SA + 128 * SA) * (int)sizeof(float);  // 87040 B
    cudaFuncSetAttribute(mlp2_mma_kernel, cudaFuncAttributeMaxDynamicSharedMemorySize, smem_mlp);

    int nblk = (N + 127) / 128;
    int eblk = (E + 255) / 256;

    // ---- fork: CSR build on side stream (independent of x) ----
    cudaEventRecord(ev_fork, 0);
    cudaStreamWaitEvent(s_side, ev_fork, 0);
    zero_cnt_kernel<<<(N + 255) / 256, 256, 0, s_side>>>(N);
    count_kernel<<<eblk, 256, 0, s_side>>>(rows, E);
    scan_kernel<<<1, 1024, 0, s_side>>>(N);
    fill_kernel<<<(E + 511) / 512, 256, 0, s_side>>>(rows, cols, vals, E);
    cudaEventRecord(ev_join, s_side);

    // ---- main stream: x = mlp1(x_in) overlaps CSR build ----
    mlp2_mma_kernel<<<nblk, THREADS, smem_mlp>>>(x_in, m1_W1, m1_b1, m1_W2, m1_b2, px, N);

    // ---- join, then aggregate + rest of pipeline ----
    cudaStreamWaitEvent(0, ev_join, 0);
    agg_kernel<<<(N * 32 + 255) / 256, 256>>>(px, pagg, N);
    mlp2_mma_kernel<<<nblk, THREADS, smem_mlp>>>(pagg, m2_W1, m2_b1, m2_W2, m2_b2, pout, N);

    dim3 grid01(nblk, 2);
    gate01_mma_kernel<<<grid01, THREADS>>>(pout, px, Wu1, bu1, Wu2, bu2,
                                           Wr1, br1, Wr2, br2, N);
    gate2_mma_kernel<<<nblk, THREADS>>>(pout, Wo1, bo1, prx, Wo2, bo2, (float*)d_out, N);
}

// round 7
// speedup vs baseline: 2.8989x; 1.1267x over previous
#include <cuda_runtime.h>
#include <math.h>
#include <stdint.h>

#define D     128
#define D4    32
#define NMAX  50000
#define EMAX  1600000
#define BK    16
#define THREADS 256
#define SB    136   // B smem row stride (floats): proven conflict-free fragment banks
#define SAR   20    // A row-major smem stride: (20g+tig)%32 bijective -> conflict-free

// -------- device scratch (allocation-free rule: __device__ globals) --------
__device__ float g_x[NMAX * D];      // fp32 x (epilogue math)
__device__ float g_xtf[NMAX * D];    // tf32-rounded x (GEMM A input)
__device__ float g_xin[NMAX * D];    // tf32-rounded x_in
__device__ float g_agg[NMAX * D];    // tf32-rounded agg
__device__ float g_out[NMAX * D];    // tf32-rounded out
__device__ float g_z[NMAX * D];      // fp32 z
__device__ float g_rx[NMAX * D];     // tf32-rounded r*x
__device__ float g_wtf[10 * D * D];  // tf32-rounded weights
__device__ int   g_cnt[NMAX];
__device__ int   g_start[NMAX + 1];
__device__ int   g_cur[NMAX];
__device__ int2  g_edges[EMAX];

__device__ __forceinline__ float sigf(float x) { return 1.0f / (1.0f + expf(-x)); }

__device__ __forceinline__ uint32_t f2tf32(float f) {
    uint32_t u;
    asm("cvt.rna.tf32.f32 %0, %1;" : "=r"(u) : "f"(f));
    return u;
}
__device__ __forceinline__ float rtf(float f) { return __uint_as_float(f2tf32(f)); }

__device__ __forceinline__ void mma_tf32(float c[4], const uint32_t a[4],
                                         uint32_t b0, uint32_t b1) {
    asm volatile(
        "mma.sync.aligned.m16n8k8.row.col.f32.tf32.tf32.f32 "
        "{%0,%1,%2,%3}, {%4,%5,%6,%7}, {%8,%9}, {%0,%1,%2,%3};"
        : "+f"(c[0]), "+f"(c[1]), "+f"(c[2]), "+f"(c[3])
        : "r"(a[0]), "r"(a[1]), "r"(a[2]), "r"(a[3]), "r"(b0), "r"(b1));
}

// ---- cp.async helpers ----
__device__ __forceinline__ void cp16(void* dst_smem, const void* src, bool pred) {
    uint32_t dst = (uint32_t)__cvta_generic_to_shared(dst_smem);
    int sz = pred ? 16 : 0;
    asm volatile("cp.async.ca.shared.global [%0], [%1], 16, %2;\n"
                 :: "r"(dst), "l"(src), "r"(sz));
}
__device__ __forceinline__ void cp_commit() {
    asm volatile("cp.async.commit_group;\n");
}
template <int N>
__device__ __forceinline__ void cp_wait() {
    asm volatile("cp.async.wait_group %0;\n" :: "n"(N));
}

// A chunk [row0..+128) x [k0..+16) -> Abuf[row][k] row-major (raw copy; data pre-rounded)
__device__ __forceinline__ void cpA(const float* __restrict__ A, int row0, int Nrows,
                                    int k0, float* Abuf, int tid) {
#pragma unroll
    for (int q = 0; q < 2; ++q) {
        int idx = tid + q * 256;
        int row = idx >> 2;
        int kq  = (idx & 3) << 2;
        cp16(Abuf + row * SAR + kq,
             A + (size_t)(row0 + row) * D + k0 + kq,
             row0 + row < Nrows);
    }
}

// W chunk [k0..+16) x [0..128) -> Bbuf[k][c] (raw copy; weights pre-rounded)
__device__ __forceinline__ void cpB(const float* __restrict__ W, int k0,
                                    float* Bbuf, int tid) {
#pragma unroll
    for (int q = 0; q < 2; ++q) {
        int idx = tid + q * 256;
        int k  = idx >> 5;
        int c4 = (idx & 31) << 2;
        cp16(Bbuf + k * SB + c4, W + (size_t)(k0 + k) * D + c4, true);
    }
}

// ---- mma over one 16-k chunk; A in row-major smem (stride SAR) ----
__device__ __forceinline__ void mma_chunk_rowA(const float* Ar, const float* Bs,
                                               int m_base, int n_base, int g, int tig,
                                               float acc[2][8][4]) {
#pragma unroll
    for (int ks = 0; ks < 2; ++ks) {
        int k = ks * 8;
        uint32_t afr[2][4];
#pragma unroll
        for (int mt = 0; mt < 2; ++mt) {
            const float* b0p = Ar + (m_base + mt * 16 + g) * SAR + k;
            const float* b1p = b0p + 8 * SAR;
            afr[mt][0] = __float_as_uint(b0p[tig]);
            afr[mt][1] = __float_as_uint(b1p[tig]);
            afr[mt][2] = __float_as_uint(b0p[tig + 4]);
            afr[mt][3] = __float_as_uint(b1p[tig + 4]);
        }
#pragma unroll
        for (int nt = 0; nt < 8; ++nt) {
            int nc = n_base + nt * 8 + g;
            uint32_t b0 = __float_as_uint(Bs[(k + tig) * SB + nc]);
            uint32_t b1 = __float_as_uint(Bs[(k + tig + 4) * SB + nc]);
            mma_tf32(acc[0][nt], afr[0], b0, b1);
            mma_tf32(acc[1][nt], afr[1], b0, b1);
        }
    }
}

// ---- mma over one 16-k chunk; A in [k][row] smem (stride SB) — for Hs ----
__device__ __forceinline__ void mma_chunk_colA(const float* As, const float* Bs,
                                               int kk_a, int m_base, int n_base,
                                               int g, int tig, float acc[2][8][4]) {
#pragma unroll
    for (int ks = 0; ks < 2; ++ks) {
        int ka = kk_a + ks * 8;
        int kb = ks * 8;
        uint32_t afr[2][4];
#pragma unroll
        for (int mt = 0; mt < 2; ++mt) {
            int mr = m_base + mt * 16 + g;
            afr[mt][0] = __float_as_uint(As[(ka + tig)     * SB + mr]);
            afr[mt][1] = __float_as_uint(As[(ka + tig)     * SB + mr + 8]);
            afr[mt][2] = __float_as_uint(As[(ka + tig + 4) * SB + mr]);
            afr[mt][3] = __float_as_uint(As[(ka + tig + 4) * SB + mr + 8]);
        }
#pragma unroll
        for (int nt = 0; nt < 8; ++nt) {
            int nc = n_base + nt * 8 + g;
            uint32_t b0 = __float_as_uint(Bs[(kb + tig)     * SB + nc]);
            uint32_t b1 = __float_as_uint(Bs[(kb + tig + 4) * SB + nc]);
            mma_tf32(acc[0][nt], afr[0], b0, b1);
            mma_tf32(acc[1][nt], afr[1], b0, b1);
        }
    }
}

#define ABUF_F (128 * SAR)   // 2560 floats per A buffer
#define BBUF_F (BK * SB)     // 2176 floats per B buffer

// ===========================================================================
// Fused 2-layer MLP on tensor cores with cp.async double buffering.
// DUAL: write fp32 to O and tf32-rounded to O2. else: tf32-rounded to O.
// ===========================================================================
template <bool DUAL>
__global__ void __launch_bounds__(THREADS, 2)
mlp2_mma_kernel(const float* __restrict__ A,
                const float* __restrict__ W1, const float* __restrict__ b1,
                const float* __restrict__ W2, const float* __restrict__ b2,
                float* __restrict__ O, float* __restrict__ O2, int Nrows)
{
    extern __shared__ float sm[];
    float* Ab[2] = {sm, sm + ABUF_F};
    float* Bb[2] = {sm + 2 * ABUF_F, sm + 2 * ABUF_F + BBUF_F};
    float* Hs = sm + 2 * ABUF_F + 2 * BBUF_F;   // 128*SB floats

    int tid  = threadIdx.x;
    int warp = tid >> 5;
    int lane = tid & 31;
    int g    = lane >> 2;
    int tig  = lane & 3;
    int m_base = (warp >> 1) * 32;
    int n_base = (warp & 1) * 64;
    int row0 = blockIdx.x * 128;

    float acc[2][8][4];
#pragma unroll
    for (int mt = 0; mt < 2; ++mt)
#pragma unroll
        for (int nt = 0; nt < 8; ++nt)
#pragma unroll
            for (int i = 0; i < 4; ++i) acc[mt][nt][i] = 0.f;

    // ---- layer 1: A @ W1 (A + B double-buffered) ----
    cpA(A, row0, Nrows, 0, Ab[0], tid);
    cpB(W1, 0, Bb[0], tid);
    cp_commit();
#pragma unroll 1
    for (int kc = 0; kc < 8; ++kc) {
        if (kc < 7) {
            cpA(A, row0, Nrows, (kc + 1) * BK, Ab[(kc + 1) & 1], tid);
            cpB(W1, (kc + 1) * BK, Bb[(kc + 1) & 1], tid);
            cp_commit();
            cp_wait<1>();
        } else {
            cp_wait<0>();
        }
        __syncthreads();
        mma_chunk_rowA(Ab[kc & 1], Bb[kc & 1], m_base, n_base, g, tig, acc);
        __syncthreads();
    }

    // prefetch W2 chunk0 (Bb[0] free: last read at kc=6, sync'd)
    cpB(W2, 0, Bb[0], tid);
    cp_commit();

    // ---- epilogue 1: relu(acc + b1) -> Hs[k][row] tf32 ----
#pragma unroll
    for (int nt = 0; nt < 8; ++nt) {
        int col = n_base + nt * 8 + 2 * tig;
        float bx = __ldg(&b1[col]);
        float by = __ldg(&b1[col + 1]);
#pragma unroll
        for (int mt = 0; mt < 2; ++mt) {
#pragma unroll
            for (int h = 0; h < 2; ++h) {
                int row = m_base + mt * 16 + g + h * 8;
                Hs[col * SB + row]       = rtf(fmaxf(acc[mt][nt][2 * h]     + bx, 0.f));
                Hs[(col + 1) * SB + row] = rtf(fmaxf(acc[mt][nt][2 * h + 1] + by, 0.f));
                acc[mt][nt][2 * h] = 0.f;
                acc[mt][nt][2 * h + 1] = 0.f;
            }
        }
    }
    __syncthreads();

    // ---- layer 2: Hs @ W2 (B double-buffered) ----
#pragma unroll 1
    for (int kc = 0; kc < 8; ++kc) {
        if (kc < 7) {
            cpB(W2, (kc + 1) * BK, Bb[(kc + 1) & 1], tid);
            cp_commit();
            cp_wait<1>();
        } else {
            cp_wait<0>();
        }
        __syncthreads();
        mma_chunk_colA(Hs, Bb[kc & 1], kc * BK, m_base, n_base, g, tig, acc);
        __syncthreads();
    }

    // ---- epilogue 2 ----
#pragma unroll
    for (int nt = 0; nt < 8; ++nt) {
        int col = n_base + nt * 8 + 2 * tig;
        float2 bb = make_float2(__ldg(&b2[col]), __ldg(&b2[col + 1]));
#pragma unroll
        for (int mt = 0; mt < 2; ++mt) {
#pragma unroll
            for (int h = 0; h < 2; ++h) {
                int row = row0 + m_base + mt * 16 + g + h * 8;
                if (row >= Nrows) continue;
                float vx = acc[mt][nt][2 * h]     + bb.x;
                float vy = acc[mt][nt][2 * h + 1] + bb.y;
                if (DUAL) {
                    *reinterpret_cast<float2*>(&O[(size_t)row * D + col]) =
                        make_float2(vx, vy);
                    *reinterpret_cast<float2*>(&O2[(size_t)row * D + col]) =
                        make_float2(rtf(vx), rtf(vy));
                } else {
                    *reinterpret_cast<float2*>(&O[(size_t)row * D + col]) =
                        make_float2(rtf(vx), rtf(vy));
                }
            }
        }
    }
}

// ===========================================================================
// Dual-GEMM accumulate with cp.async double buffering (16 flattened chunks).
// ===========================================================================
__device__ __forceinline__ void dual_gemm_ca(const float* A1, const float* W1t,
                                             const float* A2, const float* W2t,
                                             float* smA, float* smB,
                                             int row0, int Nrows, int tid,
                                             int m_base, int n_base, int g, int tig,
                                             float acc[2][8][4]) {
    const float* Aarr[2] = {A1, A2};
    const float* Warr[2] = {W1t, W2t};
    float* Ab[2] = {smA, smA + ABUF_F};
    float* Bb[2] = {smB, smB + BBUF_F};

    cpA(Aarr[0], row0, Nrows, 0, Ab[0], tid);
    cpB(Warr[0], 0, Bb[0], tid);
    cp_commit();
#pragma unroll 1
    for (int t = 0; t < 16; ++t) {
        if (t < 15) {
            int tp = t + 1;
            cpA(Aarr[tp >> 3], row0, Nrows, (tp & 7) * BK, Ab[tp & 1], tid);
            cpB(Warr[tp >> 3], (tp & 7) * BK, Bb[tp & 1], tid);
            cp_commit();
            cp_wait<1>();
        } else {
            cp_wait<0>();
        }
        __syncthreads();
        mma_chunk_rowA(Ab[t & 1], Bb[t & 1], m_base, n_base, g, tig, acc);
        __syncthreads();
    }
}

// Merged z/r gate kernel (gridDim.y = 2).
__global__ void __launch_bounds__(THREADS, 2)
gate01_mma_kernel(const float* __restrict__ out_, const float* __restrict__ xtf_,
                  const float* __restrict__ wtf,
                  const float* __restrict__ bu1, const float* __restrict__ bu2,
                  const float* __restrict__ br1, const float* __restrict__ br2,
                  int Nrows)
{
    __shared__ float smA[2 * ABUF_F];
    __shared__ float smB[2 * BBUF_F];

    int mode = blockIdx.y;
    const float* Wa = wtf + (size_t)(4 + 2 * mode) * D * D;
    const float* Wb = wtf + (size_t)(5 + 2 * mode) * D * D;
    const float* ba = mode ? br1 : bu1;
    const float* bb_ = mode ? br2 : bu2;

    int tid  = threadIdx.x;
    int warp = tid >> 5;
    int lane = tid & 31;
    int g    = lane >> 2;
    int tig  = lane & 3;
    int m_base = (warp >> 1) * 32;
    int n_base = (warp & 1) * 64;
    int row0 = blockIdx.x * 128;

    float acc[2][8][4];
#pragma unroll
    for (int mt = 0; mt < 2; ++mt)
#pragma unroll
        for (int nt = 0; nt < 8; ++nt)
#pragma unroll
            for (int i = 0; i < 4; ++i) acc[mt][nt][i] = 0.f;

    dual_gemm_ca(out_, Wa, xtf_, Wb, smA, smB, row0, Nrows, tid,
                 m_base, n_base, g, tig, acc);

    const float2* x2 = reinterpret_cast<const float2*>(g_x);
#pragma unroll
    for (int nt = 0; nt < 8; ++nt) {
        int col = n_base + nt * 8 + 2 * tig;
        float2 bsum;
        bsum.x = __ldg(&ba[col])     + __ldg(&bb_[col]);
        bsum.y = __ldg(&ba[col + 1]) + __ldg(&bb_[col + 1]);
#pragma unroll
        for (int mt = 0; mt < 2; ++mt) {
#pragma unroll
            for (int h = 0; h < 2; ++h) {
                int row = row0 + m_base + mt * 16 + g + h * 8;
                if (row >= Nrows) continue;
                float sx = sigf(acc[mt][nt][2 * h]     + bsum.x);
                float sy = sigf(acc[mt][nt][2 * h + 1] + bsum.y);
                size_t p = (size_t)row * 64 + (col >> 1);
                if (mode == 0) {
                    reinterpret_cast<float2*>(g_z)[p] = make_float2(sx, sy);
                } else {
                    float2 xv = x2[p];
                    reinterpret_cast<float2*>(g_rx)[p] =
                        make_float2(rtf(sx * xv.x), rtf(sy * xv.y));
                }
            }
        }
    }
}

// Final gate: O = (1-z)*x + z*tanh(out@Wo1 + rx@Wo2 + bo1 + bo2)
__global__ void __launch_bounds__(THREADS, 2)
gate2_mma_kernel(const float* __restrict__ out_, const float* __restrict__ rx_,
                 const float* __restrict__ wtf,
                 const float* __restrict__ bo1, const float* __restrict__ bo2,
                 float* __restrict__ O, int Nrows)
{
    __shared__ float smA[2 * ABUF_F];
    __shared__ float smB[2 * BBUF_F];

    const float* Wa = wtf + (size_t)8 * D * D;
    const float* Wb = wtf + (size_t)9 * D * D;

    int tid  = threadIdx.x;
    int warp = tid >> 5;
    int lane = tid & 31;
    int g    = lane >> 2;
    int tig  = lane & 3;
    int m_base = (warp >> 1) * 32;
    int n_base = (warp & 1) * 64;
    int row0 = blockIdx.x * 128;

    float acc[2][8][4];
#pragma unroll
    for (int mt = 0; mt < 2; ++mt)
#pragma unroll
        for (int nt = 0; nt < 8; ++nt)
#pragma unroll
            for (int i = 0; i < 4; ++i) acc[mt][nt][i] = 0.f;

    dual_gemm_ca(out_, Wa, rx_, Wb, smA, smB, row0, Nrows, tid,
                 m_base, n_base, g, tig, acc);

    const float2* x2 = reinterpret_cast<const float2*>(g_x);
    const float2* z2 = reinterpret_cast<const float2*>(g_z);
#pragma unroll
    for (int nt = 0; nt < 8; ++nt) {
        int col = n_base + nt * 8 + 2 * tig;
        float2 bsum;
        bsum.x = __ldg(&bo1[col])     + __ldg(&bo2[col]);
        bsum.y = __ldg(&bo1[col + 1]) + __ldg(&bo2[col + 1]);
#pragma unroll
        for (int mt = 0; mt < 2; ++mt) {
#pragma unroll
            for (int h = 0; h < 2; ++h) {
                int row = row0 + m_base + mt * 16 + g + h * 8;
                if (row >= Nrows) continue;
                float tx = acc[mt][nt][2 * h]     + bsum.x;
                float ty = acc[mt][nt][2 * h + 1] + bsum.y;
                size_t p = (size_t)row * 64 + (col >> 1);
                float2 xv = x2[p];
                float2 zv = z2[p];
                float2 o;
                o.x = (1.f - zv.x) * xv.x + zv.x * tanhf(tx);
                o.y = (1.f - zv.y) * xv.y + zv.y * tanhf(ty);
                reinterpret_cast<float2*>(O)[p] = o;
            }
        }
    }
}

// ===========================================================================
// Conversions
// ===========================================================================
__global__ void cvtw_kernel(const float* w0, const float* w1, const float* w2,
                            const float* w3, const float* w4, const float* w5,
                            const float* w6, const float* w7, const float* w8,
                            const float* w9, float* dst)
{
    const float* ws[10] = {w0, w1, w2, w3, w4, w5, w6, w7, w8, w9};
    const float* w = ws[blockIdx.y];
    int i = blockIdx.x * 256 + threadIdx.x;  // 16384 elems -> 64 x-blocks
    dst[(size_t)blockIdx.y * D * D + i] = rtf(w[i]);
}

__global__ void cvtx_kernel(const float* __restrict__ src, float* __restrict__ dst, int n4)
{
    int i = blockIdx.x * blockDim.x + threadIdx.x;
    if (i < n4) {
        float4 v = reinterpret_cast<const float4*>(src)[i];
        reinterpret_cast<float4*>(dst)[i] =
            make_float4(rtf(v.x), rtf(v.y), rtf(v.z), rtf(v.w));
    }
}

// ===========================================================================
// CSR build + atomic-free aggregation
// ===========================================================================
__global__ void zero_cnt_kernel(int Nn)
{
    int i = blockIdx.x * blockDim.x + threadIdx.x;
    if (i < Nn) g_cnt[i] = 0;
}

__global__ void count_kernel(const int* __restrict__ rows, int E)
{
    int e = blockIdx.x * blockDim.x + threadIdx.x;
    if (e < E) atomicAdd(&g_cnt[rows[e]], 1);
}

__global__ void scan_kernel(int Nn)
{
    __shared__ int warp_tot[32];
    int t = threadIdx.x;
    int lane = t & 31, w = t >> 5;
    int C = (Nn + 1023) / 1024;
    int lo = t * C;
    int hi = min(lo + C, Nn);

    int sum = 0;
    for (int i = lo; i < hi; ++i) sum += g_cnt[i];

    int v = sum;
#pragma unroll
    for (int o = 1; o < 32; o <<= 1) {
        int u = __shfl_up_sync(0xffffffffu, v, o);
        if (lane >= o) v += u;
    }
    if (lane == 31) warp_tot[w] = v;
    __syncthreads();
    if (w == 0) {
        int tv = warp_tot[lane];
#pragma unroll
        for (int o = 1; o < 32; o <<= 1) {
            int u = __shfl_up_sync(0xffffffffu, tv, o);
            if (lane >= o) tv += u;
        }
        warp_tot[lane] = tv;
    }
    __syncthreads();
    int incl = v + (w > 0 ? warp_tot[w - 1] : 0);
    int run = incl - sum;

    for (int i = lo; i < hi; ++i) {
        int c = g_cnt[i];
        g_start[i] = run;
        g_cur[i] = run;
        run += c;
    }
    if (t == 1023) g_start[Nn] = run;
}

__global__ void fill_kernel(const int* __restrict__ rows, const int* __restrict__ cols,
                            const float* __restrict__ vals, int E)
{
    int e = blockIdx.x * blockDim.x + threadIdx.x;
    if (e < E) {
        int r = rows[e];
        int pos = atomicAdd(&g_cur[r], 1);
        g_edges[pos] = make_int2(cols[e], __float_as_int(vals[e]));
    }
}

// Warp per node; output tf32-rounded (GEMM input).
__global__ void agg_kernel(const float* __restrict__ x, float* __restrict__ agg, int Nn)
{
    int gw = (blockIdx.x * blockDim.x + threadIdx.x) >> 5;
    int lane = threadIdx.x & 31;
    if (gw >= Nn) return;

    int s = __ldg(&g_start[gw]);
    int t = __ldg(&g_start[gw + 1]);
    const float4* x4 = reinterpret_cast<const float4*>(x);

    float4 acc = make_float4(0.f, 0.f, 0.f, 0.f);
    int j = s;
    for (; j + 2 <= t; j += 2) {
        int2 ea = __ldg(&g_edges[j]);
        int2 eb = __ldg(&g_edges[j + 1]);
        float4 xa = x4[(size_t)ea.x * D4 + lane];
        float4 xb = x4[(size_t)eb.x * D4 + lane];
        float va = __int_as_float(ea.y);
        float vb = __int_as_float(eb.y);
        acc.x += va * xa.x; acc.y += va * xa.y; acc.z += va * xa.z; acc.w += va * xa.w;
        acc.x += vb * xb.x; acc.y += vb * xb.y; acc.z += vb * xb.z; acc.w += vb * xb.w;
    }
    if (j < t) {
        int2 ea = __ldg(&g_edges[j]);
        float4 xa = x4[(size_t)ea.x * D4 + lane];
        float va = __int_as_float(ea.y);
        acc.x += va * xa.x; acc.y += va * xa.y; acc.z += va * xa.z; acc.w += va * xa.w;
    }
    reinterpret_cast<float4*>(agg)[(size_t)gw * D4 + lane] =
        make_float4(rtf(acc.x), rtf(acc.y), rtf(acc.z), rtf(acc.w));
}

// ---------------------------------------------------------------------------
extern "C" void kernel_launch(void* const* d_in, const int* in_sizes, int n_in,
                              void* d_out, int out_size)
{
    const float* x_in  = (const float*)d_in[0];
    const int*   rows  = (const int*)  d_in[1];
    const int*   cols  = (const int*)  d_in[2];
    const float* vals  = (const float*)d_in[3];
    const float* m1_W1 = (const float*)d_in[4];
    const float* m1_b1 = (const float*)d_in[5];
    const float* m1_W2 = (const float*)d_in[6];
    const float* m1_b2 = (const float*)d_in[7];
    const float* m2_W1 = (const float*)d_in[8];
    const float* m2_b1 = (const float*)d_in[9];
    const float* m2_W2 = (const float*)d_in[10];
    const float* m2_b2 = (const float*)d_in[11];
    const float* bu1   = (const float*)d_in[13];
    const float* bu2   = (const float*)d_in[15];
    const float* br1   = (const float*)d_in[17];
    const float* br2   = (const float*)d_in[19];
    const float* bo1   = (const float*)d_in[21];
    const float* bo2   = (const float*)d_in[23];
    const float* Wu1   = (const float*)d_in[12];
    const float* Wu2   = (const float*)d_in[14];
    const float* Wr1   = (const float*)d_in[16];
    const float* Wr2   = (const float*)d_in[18];
    const float* Wo1   = (const float*)d_in[20];
    const float* Wo2   = (const float*)d_in[22];

    int N = in_sizes[0] / D;
    int E = in_sizes[1];

    float *px, *pxtf, *pxin, *pagg, *pout, *prx, *pwtf;
    cudaGetSymbolAddress((void**)&px,   g_x);
    cudaGetSymbolAddress((void**)&pxtf, g_xtf);
    cudaGetSymbolAddress((void**)&pxin, g_xin);
    cudaGetSymbolAddress((void**)&pagg, g_agg);
    cudaGetSymbolAddress((void**)&pout, g_out);
    cudaGetSymbolAddress((void**)&prx,  g_rx);
    cudaGetSymbolAddress((void**)&pwtf, g_wtf);

    static cudaStream_t s_side = nullptr;
    static cudaEvent_t ev_fork = nullptr, ev_join = nullptr;
    if (!s_side) {
        cudaStreamCreateWithFlags(&s_side, cudaStreamNonBlocking);
        cudaEventCreateWithFlags(&ev_fork, cudaEventDisableTiming);
        cudaEventCreateWithFlags(&ev_join, cudaEventDisableTiming);
    }

    int smem_mlp = (2 * ABUF_F + 2 * BBUF_F + 128 * SB) * (int)sizeof(float);  // 107520 B
    cudaFuncSetAttribute(mlp2_mma_kernel<true>,  cudaFuncAttributeMaxDynamicSharedMemorySize, smem_mlp);
    cudaFuncSetAttribute(mlp2_mma_kernel<false>, cudaFuncAttributeMaxDynamicSharedMemorySize, smem_mlp);

    int nblk = (N + 127) / 128;
    int eblk = (E + 255) / 256;
    int n4 = N * D / 4;

    // ---- fork: CSR build on side stream ----
    cudaEventRecord(ev_fork, 0);
    cudaStreamWaitEvent(s_side, ev_fork, 0);
    zero_cnt_kernel<<<(N + 255) / 256, 256, 0, s_side>>>(N);
    count_kernel<<<eblk, 256, 0, s_side>>>(rows, E);
    scan_kernel<<<1, 1024, 0, s_side>>>(N);
    fill_kernel<<<eblk, 256, 0, s_side>>>(rows, cols, vals, E);
    cudaEventRecord(ev_join, s_side);

    // ---- main: conversions, then pipeline ----
    dim3 wgrid(64, 10);
    cvtw_kernel<<<wgrid, 256>>>(m1_W1, m1_W2, m2_W1, m2_W2, Wu1, Wu2, Wr1, Wr2, Wo1, Wo2, pwtf);
    cvtx_kernel<<<(n4 + 255) / 256, 256>>>(x_in, pxin, n4);

    mlp2_mma_kernel<true><<<nblk, THREADS, smem_mlp>>>(
        pxin, pwtf + 0 * D * D, m1_b1, pwtf + 1 * D * D, m1_b2, px, pxtf, N);

    cudaStreamWaitEvent(0, ev_join, 0);
    agg_kernel<<<(N * 32 + 255) / 256, 256>>>(pxtf, pagg, N);

    mlp2_mma_kernel<false><<<nblk, THREADS, smem_mlp>>>(
        pagg, pwtf + 2 * D * D, m2_b1, pwtf + 3 * D * D, m2_b2, pout, nullptr, N);

    dim3 grid01(nblk, 2);
    gate01_mma_kernel<<<grid01, THREADS>>>(pout, pxtf, pwtf, bu1, bu2, br1, br2, N);
    gate2_mma_kernel<<<nblk, THREADS>>>(pout, prx, pwtf, bo1, bo2, (float*)d_out, N);
}

// round 8
// speedup vs baseline: 2.9173x; 1.0063x over previous
#include <cuda_runtime.h>
#include <cuda_fp16.h>
#include <math.h>
#include <stdint.h>

#define D     128
#define D4    32
#define NMAX  50000
#define EMAX  1600000
#define BK    16
#define THREADS 256
#define SB    136   // B smem row stride (floats): proven conflict-free fragment banks
#define SAR   20    // A row-major smem stride: (20g+tig)%32 bijective -> conflict-free

// -------- device scratch (allocation-free rule: __device__ globals) --------
__device__ float  g_x[NMAX * D];      // fp32 x (epilogue math)
__device__ float  g_xtf[NMAX * D];    // tf32-rounded x (GEMM A input)
__device__ __half g_xh[NMAX * D];     // fp16 x (agg gather)
__device__ float  g_xin[NMAX * D];    // tf32-rounded x_in
__device__ float  g_agg[NMAX * D];    // tf32-rounded agg
__device__ float  g_out[NMAX * D];    // tf32-rounded out
__device__ float  g_z[NMAX * D];      // fp32 z
__device__ float  g_rx[NMAX * D];     // tf32-rounded r*x
__device__ float  g_wtf[10 * D * D];  // tf32-rounded weights
__device__ int    g_cnt[NMAX];
__device__ int    g_start[NMAX + 1];
__device__ int    g_cur[NMAX];
__device__ int2   g_edges[EMAX];

__device__ __forceinline__ float sigf(float x) { return 1.0f / (1.0f + expf(-x)); }

__device__ __forceinline__ uint32_t f2tf32(float f) {
    uint32_t u;
    asm("cvt.rna.tf32.f32 %0, %1;" : "=r"(u) : "f"(f));
    return u;
}
__device__ __forceinline__ float rtf(float f) { return __uint_as_float(f2tf32(f)); }

__device__ __forceinline__ void mma_tf32(float c[4], const uint32_t a[4],
                                         uint32_t b0, uint32_t b1) {
    asm volatile(
        "mma.sync.aligned.m16n8k8.row.col.f32.tf32.tf32.f32 "
        "{%0,%1,%2,%3}, {%4,%5,%6,%7}, {%8,%9}, {%0,%1,%2,%3};"
        : "+f"(c[0]), "+f"(c[1]), "+f"(c[2]), "+f"(c[3])
        : "r"(a[0]), "r"(a[1]), "r"(a[2]), "r"(a[3]), "r"(b0), "r"(b1));
}

// ---- cp.async helpers ----
__device__ __forceinline__ void cp16(void* dst_smem, const void* src, bool pred) {
    uint32_t dst = (uint32_t)__cvta_generic_to_shared(dst_smem);
    int sz = pred ? 16 : 0;
    asm volatile("cp.async.ca.shared.global [%0], [%1], 16, %2;\n"
                 :: "r"(dst), "l"(src), "r"(sz));
}
__device__ __forceinline__ void cp_commit() {
    asm volatile("cp.async.commit_group;\n");
}
template <int N>
__device__ __forceinline__ void cp_wait() {
    asm volatile("cp.async.wait_group %0;\n" :: "n"(N));
}

// A chunk [row0..+128) x [k0..+16) -> Abuf[row][k] row-major
__device__ __forceinline__ void cpA(const float* __restrict__ A, int row0, int Nrows,
                                    int k0, float* Abuf, int tid) {
#pragma unroll
    for (int q = 0; q < 2; ++q) {
        int idx = tid + q * 256;
        int row = idx >> 2;
        int kq  = (idx & 3) << 2;
        cp16(Abuf + row * SAR + kq,
             A + (size_t)(row0 + row) * D + k0 + kq,
             row0 + row < Nrows);
    }
}

// W chunk [k0..+16) x [0..128) -> Bbuf[k][c]
__device__ __forceinline__ void cpB(const float* __restrict__ W, int k0,
                                    float* Bbuf, int tid) {
#pragma unroll
    for (int q = 0; q < 2; ++q) {
        int idx = tid + q * 256;
        int k  = idx >> 5;
        int c4 = (idx & 31) << 2;
        cp16(Bbuf + k * SB + c4, W + (size_t)(k0 + k) * D + c4, true);
    }
}

// ---- mma over one 16-k chunk; A in row-major smem (stride SAR) ----
__device__ __forceinline__ void mma_chunk_rowA(const float* Ar, const float* Bs,
                                               int m_base, int n_base, int g, int tig,
                                               float acc[2][8][4]) {
#pragma unroll
    for (int ks = 0; ks < 2; ++ks) {
        int k = ks * 8;
        uint32_t afr[2][4];
#pragma unroll
        for (int mt = 0; mt < 2; ++mt) {
            const float* b0p = Ar + (m_base + mt * 16 + g) * SAR + k;
            const float* b1p = b0p + 8 * SAR;
            afr[mt][0] = __float_as_uint(b0p[tig]);
            afr[mt][1] = __float_as_uint(b1p[tig]);
            afr[mt][2] = __float_as_uint(b0p[tig + 4]);
            afr[mt][3] = __float_as_uint(b1p[tig + 4]);
        }
#pragma unroll
        for (int nt = 0; nt < 8; ++nt) {
            int nc = n_base + nt * 8 + g;
            uint32_t b0 = __float_as_uint(Bs[(k + tig) * SB + nc]);
            uint32_t b1 = __float_as_uint(Bs[(k + tig + 4) * SB + nc]);
            mma_tf32(acc[0][nt], afr[0], b0, b1);
            mma_tf32(acc[1][nt], afr[1], b0, b1);
        }
    }
}

// ---- mma over one 16-k chunk; A in [k][row] smem (stride SB) — for Hs ----
__device__ __forceinline__ void mma_chunk_colA(const float* As, const float* Bs,
                                               int kk_a, int m_base, int n_base,
                                               int g, int tig, float acc[2][8][4]) {
#pragma unroll
    for (int ks = 0; ks < 2; ++ks) {
        int ka = kk_a + ks * 8;
        int kb = ks * 8;
        uint32_t afr[2][4];
#pragma unroll
        for (int mt = 0; mt < 2; ++mt) {
            int mr = m_base + mt * 16 + g;
            afr[mt][0] = __float_as_uint(As[(ka + tig)     * SB + mr]);
            afr[mt][1] = __float_as_uint(As[(ka + tig)     * SB + mr + 8]);
            afr[mt][2] = __float_as_uint(As[(ka + tig + 4) * SB + mr]);
            afr[mt][3] = __float_as_uint(As[(ka + tig + 4) * SB + mr + 8]);
        }
#pragma unroll
        for (int nt = 0; nt < 8; ++nt) {
            int nc = n_base + nt * 8 + g;
            uint32_t b0 = __float_as_uint(Bs[(kb + tig)     * SB + nc]);
            uint32_t b1 = __float_as_uint(Bs[(kb + tig + 4) * SB + nc]);
            mma_tf32(acc[0][nt], afr[0], b0, b1);
            mma_tf32(acc[1][nt], afr[1], b0, b1);
        }
    }
}

#define ABUF_F (128 * SAR)   // 2560 floats per A buffer
#define BBUF_F (BK * SB)     // 2176 floats per B buffer

// ===========================================================================
// Fused 2-layer MLP on tensor cores, cp.async 2-stage (R7-proven).
// DUAL: write fp32 to O, tf32 to O2, fp16 to OH.
// ===========================================================================
template <bool DUAL>
__global__ void __launch_bounds__(THREADS, 2)
mlp2_mma_kernel(const float* __restrict__ A,
                const float* __restrict__ W1, const float* __restrict__ b1,
                const float* __restrict__ W2, const float* __restrict__ b2,
                float* __restrict__ O, float* __restrict__ O2,
                __half* __restrict__ OH, int Nrows)
{
    extern __shared__ float sm[];
    float* Ab[2] = {sm, sm + ABUF_F};
    float* Bb[2] = {sm + 2 * ABUF_F, sm + 2 * ABUF_F + BBUF_F};
    float* Hs = sm + 2 * ABUF_F + 2 * BBUF_F;

    int tid  = threadIdx.x;
    int warp = tid >> 5;
    int lane = tid & 31;
    int g    = lane >> 2;
    int tig  = lane & 3;
    int m_base = (warp >> 1) * 32;
    int n_base = (warp & 1) * 64;
    int row0 = blockIdx.x * 128;

    float acc[2][8][4];
#pragma unroll
    for (int mt = 0; mt < 2; ++mt)
#pragma unroll
        for (int nt = 0; nt < 8; ++nt)
#pragma unroll
            for (int i = 0; i < 4; ++i) acc[mt][nt][i] = 0.f;

    cpA(A, row0, Nrows, 0, Ab[0], tid);
    cpB(W1, 0, Bb[0], tid);
    cp_commit();
#pragma unroll 1
    for (int kc = 0; kc < 8; ++kc) {
        if (kc < 7) {
            cpA(A, row0, Nrows, (kc + 1) * BK, Ab[(kc + 1) & 1], tid);
            cpB(W1, (kc + 1) * BK, Bb[(kc + 1) & 1], tid);
            cp_commit();
            cp_wait<1>();
        } else {
            cp_wait<0>();
        }
        __syncthreads();
        mma_chunk_rowA(Ab[kc & 1], Bb[kc & 1], m_base, n_base, g, tig, acc);
        __syncthreads();
    }

    cpB(W2, 0, Bb[0], tid);
    cp_commit();

#pragma unroll
    for (int nt = 0; nt < 8; ++nt) {
        int col = n_base + nt * 8 + 2 * tig;
        float bx = __ldg(&b1[col]);
        float by = __ldg(&b1[col + 1]);
#pragma unroll
        for (int mt = 0; mt < 2; ++mt) {
#pragma unroll
            for (int h = 0; h < 2; ++h) {
                int row = m_base + mt * 16 + g + h * 8;
                Hs[col * SB + row]       = rtf(fmaxf(acc[mt][nt][2 * h]     + bx, 0.f));
                Hs[(col + 1) * SB + row] = rtf(fmaxf(acc[mt][nt][2 * h + 1] + by, 0.f));
                acc[mt][nt][2 * h] = 0.f;
                acc[mt][nt][2 * h + 1] = 0.f;
            }
        }
    }
    __syncthreads();

#pragma unroll 1
    for (int kc = 0; kc < 8; ++kc) {
        if (kc < 7) {
            cpB(W2, (kc + 1) * BK, Bb[(kc + 1) & 1], tid);
            cp_commit();
            cp_wait<1>();
        } else {
            cp_wait<0>();
        }
        __syncthreads();
        mma_chunk_colA(Hs, Bb[kc & 1], kc * BK, m_base, n_base, g, tig, acc);
        __syncthreads();
    }

#pragma unroll
    for (int nt = 0; nt < 8; ++nt) {
        int col = n_base + nt * 8 + 2 * tig;
        float2 bb = make_float2(__ldg(&b2[col]), __ldg(&b2[col + 1]));
#pragma unroll
        for (int mt = 0; mt < 2; ++mt) {
#pragma unroll
            for (int h = 0; h < 2; ++h) {
                int row = row0 + m_base + mt * 16 + g + h * 8;
                if (row >= Nrows) continue;
                float vx = acc[mt][nt][2 * h]     + bb.x;
                float vy = acc[mt][nt][2 * h + 1] + bb.y;
                if (DUAL) {
                    *reinterpret_cast<float2*>(&O[(size_t)row * D + col]) =
                        make_float2(vx, vy);
                    *reinterpret_cast<float2*>(&O2[(size_t)row * D + col]) =
                        make_float2(rtf(vx), rtf(vy));
                    *reinterpret_cast<__half2*>(&OH[(size_t)row * D + col]) =
                        __float22half2_rn(make_float2(vx, vy));
                } else {
                    *reinterpret_cast<float2*>(&O[(size_t)row * D + col]) =
                        make_float2(rtf(vx), rtf(vy));
                }
            }
        }
    }
}

// ===========================================================================
// Dual-GEMM accumulate: cp.async 3-STAGE, ONE sync per chunk.
// Write-to-reuse distance 3 makes the trailing barrier redundant.
// ===========================================================================
__device__ __forceinline__ void dual_gemm_ca3(const float* A1, const float* W1t,
                                              const float* A2, const float* W2t,
                                              float* smA, float* smB,
                                              int row0, int Nrows, int tid,
                                              int m_base, int n_base, int g, int tig,
                                              float acc[2][8][4]) {
    const float* Aarr[2] = {A1, A2};
    const float* Warr[2] = {W1t, W2t};
    float* Ab[3] = {smA, smA + ABUF_F, smA + 2 * ABUF_F};
    float* Bb[3] = {smB, smB + BBUF_F, smB + 2 * BBUF_F};

    cpA(Aarr[0], row0, Nrows, 0, Ab[0], tid);
    cpB(Warr[0], 0, Bb[0], tid);
    cp_commit();
    cpA(Aarr[0], row0, Nrows, BK, Ab[1], tid);
    cpB(Warr[0], BK, Bb[1], tid);
    cp_commit();

#pragma unroll 1
    for (int t = 0; t < 16; ++t) {
        if (t < 15) cp_wait<1>(); else cp_wait<0>();
        __syncthreads();
        if (t < 14) {
            int tp = t + 2;
            cpA(Aarr[tp >> 3], row0, Nrows, (tp & 7) * BK, Ab[tp % 3], tid);
            cpB(Warr[tp >> 3], (tp & 7) * BK, Bb[tp % 3], tid);
            cp_commit();
        }
        mma_chunk_rowA(Ab[t % 3], Bb[t % 3], m_base, n_base, g, tig, acc);
    }
    __syncthreads();
}

// Merged z/r gate kernel (gridDim.y = 2).
__global__ void __launch_bounds__(THREADS, 2)
gate01_mma_kernel(const float* __restrict__ out_, const float* __restrict__ xtf_,
                  const float* __restrict__ wtf,
                  const float* __restrict__ bu1, const float* __restrict__ bu2,
                  const float* __restrict__ br1, const float* __restrict__ br2,
                  int Nrows)
{
    __shared__ float smA[3 * ABUF_F];
    __shared__ float smB[3 * BBUF_F];

    int mode = blockIdx.y;
    const float* Wa = wtf + (size_t)(4 + 2 * mode) * D * D;
    const float* Wb = wtf + (size_t)(5 + 2 * mode) * D * D;
    const float* ba = mode ? br1 : bu1;
    const float* bb_ = mode ? br2 : bu2;

    int tid  = threadIdx.x;
    int warp = tid >> 5;
    int lane = tid & 31;
    int g    = lane >> 2;
    int tig  = lane & 3;
    int m_base = (warp >> 1) * 32;
    int n_base = (warp & 1) * 64;
    int row0 = blockIdx.x * 128;

    float acc[2][8][4];
#pragma unroll
    for (int mt = 0; mt < 2; ++mt)
#pragma unroll
        for (int nt = 0; nt < 8; ++nt)
#pragma unroll
            for (int i = 0; i < 4; ++i) acc[mt][nt][i] = 0.f;

    dual_gemm_ca3(out_, Wa, xtf_, Wb, smA, smB, row0, Nrows, tid,
                  m_base, n_base, g, tig, acc);

    const float2* x2 = reinterpret_cast<const float2*>(g_x);
#pragma unroll
    for (int nt = 0; nt < 8; ++nt) {
        int col = n_base + nt * 8 + 2 * tig;
        float2 bsum;
        bsum.x = __ldg(&ba[col])     + __ldg(&bb_[col]);
        bsum.y = __ldg(&ba[col + 1]) + __ldg(&bb_[col + 1]);
#pragma unroll
        for (int mt = 0; mt < 2; ++mt) {
#pragma unroll
            for (int h = 0; h < 2; ++h) {
                int row = row0 + m_base + mt * 16 + g + h * 8;
                if (row >= Nrows) continue;
                float sx = sigf(acc[mt][nt][2 * h]     + bsum.x);
                float sy = sigf(acc[mt][nt][2 * h + 1] + bsum.y);
                size_t p = (size_t)row * 64 + (col >> 1);
                if (mode == 0) {
                    reinterpret_cast<float2*>(g_z)[p] = make_float2(sx, sy);
                } else {
                    float2 xv = x2[p];
                    reinterpret_cast<float2*>(g_rx)[p] =
                        make_float2(rtf(sx * xv.x), rtf(sy * xv.y));
                }
            }
        }
    }
}

// Final gate: O = (1-z)*x + z*tanh(out@Wo1 + rx@Wo2 + bo1 + bo2)
__global__ void __launch_bounds__(THREADS, 2)
gate2_mma_kernel(const float* __restrict__ out_, const float* __restrict__ rx_,
                 const float* __restrict__ wtf,
                 const float* __restrict__ bo1, const float* __restrict__ bo2,
                 float* __restrict__ O, int Nrows)
{
    __shared__ float smA[3 * ABUF_F];
    __shared__ float smB[3 * BBUF_F];

    const float* Wa = wtf + (size_t)8 * D * D;
    const float* Wb = wtf + (size_t)9 * D * D;

    int tid  = threadIdx.x;
    int warp = tid >> 5;
    int lane = tid & 31;
    int g    = lane >> 2;
    int tig  = lane & 3;
    int m_base = (warp >> 1) * 32;
    int n_base = (warp & 1) * 64;
    int row0 = blockIdx.x * 128;

    float acc[2][8][4];
#pragma unroll
    for (int mt = 0; mt < 2; ++mt)
#pragma unroll
        for (int nt = 0; nt < 8; ++nt)
#pragma unroll
            for (int i = 0; i < 4; ++i) acc[mt][nt][i] = 0.f;

    dual_gemm_ca3(out_, Wa, rx_, Wb, smA, smB, row0, Nrows, tid,
                  m_base, n_base, g, tig, acc);

    const float2* x2 = reinterpret_cast<const float2*>(g_x);
    const float2* z2 = reinterpret_cast<const float2*>(g_z);
#pragma unroll
    for (int nt = 0; nt < 8; ++nt) {
        int col = n_base + nt * 8 + 2 * tig;
        float2 bsum;
        bsum.x = __ldg(&bo1[col])     + __ldg(&bo2[col]);
        bsum.y = __ldg(&bo1[col + 1]) + __ldg(&bo2[col + 1]);
#pragma unroll
        for (int mt = 0; mt < 2; ++mt) {
#pragma unroll
            for (int h = 0; h < 2; ++h) {
                int row = row0 + m_base + mt * 16 + g + h * 8;
                if (row >= Nrows) continue;
                float tx = acc[mt][nt][2 * h]     + bsum.x;
                float ty = acc[mt][nt][2 * h + 1] + bsum.y;
                size_t p = (size_t)row * 64 + (col >> 1);
                float2 xv = x2[p];
                float2 zv = z2[p];
                float2 o;
                o.x = (1.f - zv.x) * xv.x + zv.x * tanhf(tx);
                o.y = (1.f - zv.y) * xv.y + zv.y * tanhf(ty);
                reinterpret_cast<float2*>(O)[p] = o;
            }
        }
    }
}

// ===========================================================================
// Conversions
// ===========================================================================
__global__ void cvtw_kernel(const float* w0, const float* w1, const float* w2,
                            const float* w3, const float* w4, const float* w5,
                            const float* w6, const float* w7, const float* w8,
                            const float* w9, float* dst)
{
    const float* ws[10] = {w0, w1, w2, w3, w4, w5, w6, w7, w8, w9};
    const float* w = ws[blockIdx.y];
    int i = blockIdx.x * 256 + threadIdx.x;
    dst[(size_t)blockIdx.y * D * D + i] = rtf(w[i]);
}

__global__ void cvtx_kernel(const float* __restrict__ src, float* __restrict__ dst, int n4)
{
    int i = blockIdx.x * blockDim.x + threadIdx.x;
    if (i < n4) {
        float4 v = reinterpret_cast<const float4*>(src)[i];
        reinterpret_cast<float4*>(dst)[i] =
            make_float4(rtf(v.x), rtf(v.y), rtf(v.z), rtf(v.w));
    }
}

// ===========================================================================
// CSR build + atomic-free aggregation
// ===========================================================================
__global__ void zero_cnt_kernel(int Nn)
{
    int i = blockIdx.x * blockDim.x + threadIdx.x;
    if (i < Nn) g_cnt[i] = 0;
}

__global__ void count_kernel(const int* __restrict__ rows, int E)
{
    int e = blockIdx.x * blockDim.x + threadIdx.x;
    if (e < E) atomicAdd(&g_cnt[rows[e]], 1);
}

__global__ void scan_kernel(int Nn)
{
    __shared__ int warp_tot[32];
    int t = threadIdx.x;
    int lane = t & 31, w = t >> 5;
    int C = (Nn + 1023) / 1024;
    int lo = t * C;
    int hi = min(lo + C, Nn);

    int sum = 0;
    for (int i = lo; i < hi; ++i) sum += g_cnt[i];

    int v = sum;
#pragma unroll
    for (int o = 1; o < 32; o <<= 1) {
        int u = __shfl_up_sync(0xffffffffu, v, o);
        if (lane >= o) v += u;
    }
    if (lane == 31) warp_tot[w] = v;
    __syncthreads();
    if (w == 0) {
        int tv = warp_tot[lane];
#pragma unroll
        for (int o = 1; o < 32; o <<= 1) {
            int u = __shfl_up_sync(0xffffffffu, tv, o);
            if (lane >= o) tv += u;
        }
        warp_tot[lane] = tv;
    }
    __syncthreads();
    int incl = v + (w > 0 ? warp_tot[w - 1] : 0);
    int run = incl - sum;

    for (int i = lo; i < hi; ++i) {
        int c = g_cnt[i];
        g_start[i] = run;
        g_cur[i] = run;
        run += c;
    }
    if (t == 1023) g_start[Nn] = run;
}

__global__ void fill_kernel(const int* __restrict__ rows, const int* __restrict__ cols,
                            const float* __restrict__ vals, int E)
{
    int e = blockIdx.x * blockDim.x + threadIdx.x;
    if (e < E) {
        int r = rows[e];
        int pos = atomicAdd(&g_cur[r], 1);
        g_edges[pos] = make_int2(cols[e], __float_as_int(vals[e]));
    }
}

// Warp per node; gathers fp16 x (half traffic); tf32-rounded fp32 output.
__global__ void agg_kernel(const __half* __restrict__ xh, float* __restrict__ agg, int Nn)
{
    int gw = (blockIdx.x * blockDim.x + threadIdx.x) >> 5;
    int lane = threadIdx.x & 31;
    if (gw >= Nn) return;

    int s = __ldg(&g_start[gw]);
    int t = __ldg(&g_start[gw + 1]);
    const uint2* x2 = reinterpret_cast<const uint2*>(xh);   // 4 halves per uint2

    float4 acc = make_float4(0.f, 0.f, 0.f, 0.f);
    int j = s;
    for (; j + 2 <= t; j += 2) {
        int2 ea = __ldg(&g_edges[j]);
        int2 eb = __ldg(&g_edges[j + 1]);
        uint2 ua = x2[(size_t)ea.x * 32 + lane];
        uint2 ub = x2[(size_t)eb.x * 32 + lane];
        float va = __int_as_float(ea.y);
        float vb = __int_as_float(eb.y);
        float2 a0 = __half22float2(*reinterpret_cast<__half2*>(&ua.x));
        float2 a1 = __half22float2(*reinterpret_cast<__half2*>(&ua.y));
        float2 b0 = __half22float2(*reinterpret_cast<__half2*>(&ub.x));
        float2 b1 = __half22float2(*reinterpret_cast<__half2*>(&ub.y));
        acc.x += va * a0.x; acc.y += va * a0.y; acc.z += va * a1.x; acc.w += va * a1.y;
        acc.x += vb * b0.x; acc.y += vb * b0.y; acc.z += vb * b1.x; acc.w += vb * b1.y;
    }
    if (j < t) {
        int2 ea = __ldg(&g_edges[j]);
        uint2 ua = x2[(size_t)ea.x * 32 + lane];
        float va = __int_as_float(ea.y);
        float2 a0 = __half22float2(*reinterpret_cast<__half2*>(&ua.x));
        float2 a1 = __half22float2(*reinterpret_cast<__half2*>(&ua.y));
        acc.x += va * a0.x; acc.y += va * a0.y; acc.z += va * a1.x; acc.w += va * a1.y;
    }
    reinterpret_cast<float4*>(agg)[(size_t)gw * D4 + lane] =
        make_float4(rtf(acc.x), rtf(acc.y), rtf(acc.z), rtf(acc.w));
}

// ---------------------------------------------------------------------------
extern "C" void kernel_launch(void* const* d_in, const int* in_sizes, int n_in,
                              void* d_out, int out_size)
{
    const float* x_in  = (const float*)d_in[0];
    const int*   rows  = (const int*)  d_in[1];
    const int*   cols  = (const int*)  d_in[2];
    const float* vals  = (const float*)d_in[3];
    const float* m1_W1 = (const float*)d_in[4];
    const float* m1_b1 = (const float*)d_in[5];
    const float* m1_W2 = (const float*)d_in[6];
    const float* m1_b2 = (const float*)d_in[7];
    const float* m2_W1 = (const float*)d_in[8];
    const float* m2_b1 = (const float*)d_in[9];
    const float* m2_W2 = (const float*)d_in[10];
    const float* m2_b2 = (const float*)d_in[11];
    const float* Wu1   = (const float*)d_in[12];
    const float* bu1   = (const float*)d_in[13];
    const float* Wu2   = (const float*)d_in[14];
    const float* bu2   = (const float*)d_in[15];
    const float* Wr1   = (const float*)d_in[16];
    const float* br1   = (const float*)d_in[17];
    const float* Wr2   = (const float*)d_in[18];
    const float* br2   = (const float*)d_in[19];
    const float* Wo1   = (const float*)d_in[20];
    const float* bo1   = (const float*)d_in[21];
    const float* Wo2   = (const float*)d_in[22];
    const float* bo2   = (const float*)d_in[23];

    int N = in_sizes[0] / D;
    int E = in_sizes[1];

    float *px, *pxtf, *pxin, *pagg, *pout, *prx, *pwtf;
    __half* pxh;
    cudaGetSymbolAddress((void**)&px,   g_x);
    cudaGetSymbolAddress((void**)&pxtf, g_xtf);
    cudaGetSymbolAddress((void**)&pxh,  g_xh);
    cudaGetSymbolAddress((void**)&pxin, g_xin);
    cudaGetSymbolAddress((void**)&pagg, g_agg);
    cudaGetSymbolAddress((void**)&pout, g_out);
    cudaGetSymbolAddress((void**)&prx,  g_rx);
    cudaGetSymbolAddress((void**)&pwtf, g_wtf);

    static cudaStream_t s_side = nullptr;
    static cudaEvent_t ev_fork = nullptr, ev_join = nullptr;
    if (!s_side) {
        cudaStreamCreateWithFlags(&s_side, cudaStreamNonBlocking);
        cudaEventCreateWithFlags(&ev_fork, cudaEventDisableTiming);
        cudaEventCreateWithFlags(&ev_join, cudaEventDisableTiming);
    }

    int smem_mlp = (2 * ABUF_F + 2 * BBUF_F + 128 * SB) * (int)sizeof(float);
    cudaFuncSetAttribute(mlp2_mma_kernel<true>,  cudaFuncAttributeMaxDynamicSharedMemorySize, smem_mlp);
    cudaFuncSetAttribute(mlp2_mma_kernel<false>, cudaFuncAttributeMaxDynamicSharedMemorySize, smem_mlp);

    int nblk = (N + 127) / 128;
    int eblk = (E + 255) / 256;
    int n4 = N * D / 4;

    // ---- fork: CSR build on side stream ----
    cudaEventRecord(ev_fork, 0);
    cudaStreamWaitEvent(s_side, ev_fork, 0);
    zero_cnt_kernel<<<(N + 255) / 256, 256, 0, s_side>>>(N);
    count_kernel<<<eblk, 256, 0, s_side>>>(rows, E);
    scan_kernel<<<1, 1024, 0, s_side>>>(N);
    fill_kernel<<<eblk, 256, 0, s_side>>>(rows, cols, vals, E);
    cudaEventRecord(ev_join, s_side);

    // ---- main: conversions, then pipeline ----
    dim3 wgrid(64, 10);
    cvtw_kernel<<<wgrid, 256>>>(m1_W1, m1_W2, m2_W1, m2_W2, Wu1, Wu2, Wr1, Wr2, Wo1, Wo2, pwtf);
    cvtx_kernel<<<(n4 + 255) / 256, 256>>>(x_in, pxin, n4);

    mlp2_mma_kernel<true><<<nblk, THREADS, smem_mlp>>>(
        pxin, pwtf + 0 * D * D, m1_b1, pwtf + 1 * D * D, m1_b2, px, pxtf, pxh, N);

    cudaStreamWaitEvent(0, ev_join, 0);
    agg_kernel<<<(N * 32 + 255) / 256, 256>>>(pxh, pagg, N);

    mlp2_mma_kernel<false><<<nblk, THREADS, smem_mlp>>>(
        pagg, pwtf + 2 * D * D, m2_b1, pwtf + 3 * D * D, m2_b2, pout, nullptr, nullptr, N);

    dim3 grid01(nblk, 2);
    gate01_mma_kernel<<<grid01, THREADS>>>(pout, pxtf, pwtf, bu1, bu2, br1, br2, N);
    gate2_mma_kernel<<<nblk, THREADS>>>(pout, prx, pwtf, bo1, bo2, (float*)d_out, N);
}